// round 2
// baseline (speedup 1.0000x reference)
#include <cuda_runtime.h>
#include <math.h>

#define NN   50000
#define NE   800000
#define IND  128
#define HID  256
#define OUTD 40

// ---------------- scratch (static device globals; no runtime alloc) ----------
__device__ int   g_is64;                      // 1 if edge_index is int64
__device__ int   g_counts[NN];
__device__ int   g_offsets[NN + 1];
__device__ int   g_cursor[NN];
__device__ int   g_esrc[NE];
__device__ float g_invc[NN];
__device__ __align__(16) float g_agg[(size_t)NN * IND];   // mean-agg x   [NN,128]
__device__ __align__(16) float g_h[(size_t)NN * HID];     // layer-1 act  [NN,256]
__device__ __align__(16) float g_p[(size_t)NN * OUTD];    // h @ W2_l     [NN,40]
__device__ __align__(16) float g_r[(size_t)NN * OUTD];    // h @ W2_r+b2  [NN,40]

// ---------------- edge dtype detection --------------------------------------
// If int64: values < 50000, so every odd 32-bit word of the first 1024 entries
// is 0. If int32: odd words are random in [0,50000) -> virtually never all 0.
__global__ void k_detect(const int* __restrict__ ei32) {
    __shared__ int bad;
    if (threadIdx.x == 0) bad = 0;
    __syncthreads();
    int v = ei32[2 * threadIdx.x + 1];
    if (v != 0) atomicOr(&bad, 1);
    __syncthreads();
    if (threadIdx.x == 0) g_is64 = bad ? 0 : 1;
}

__device__ __forceinline__ int edge_at(const void* ei, int idx) {
    if (g_is64) return (int)((const long long*)ei)[idx];
    return ((const int*)ei)[idx];
}

// ---------------- CSR build --------------------------------------------------
__global__ void k_zero_counts() {
    int i = blockIdx.x * blockDim.x + threadIdx.x;
    if (i < NN) g_counts[i] = 0;
}

__global__ void k_count(const void* __restrict__ ei) {
    int e = blockIdx.x * blockDim.x + threadIdx.x;
    if (e < NE) {
        int d = edge_at(ei, NE + e);
        atomicAdd(&g_counts[d], 1);
    }
}

// single-block exclusive scan over 50000 counts
__global__ void k_scan() {
    __shared__ int part[1024];
    const int CH = (NN + 1023) / 1024;   // 49
    int t = threadIdx.x;
    int base = t * CH;
    int s = 0;
    for (int i = 0; i < CH; i++) {
        int idx = base + i;
        if (idx < NN) s += g_counts[idx];
    }
    part[t] = s;
    __syncthreads();
    for (int off = 1; off < 1024; off <<= 1) {
        int v = (t >= off) ? part[t - off] : 0;
        __syncthreads();
        part[t] += v;
        __syncthreads();
    }
    int run = (t > 0) ? part[t - 1] : 0;
    for (int i = 0; i < CH; i++) {
        int idx = base + i;
        if (idx < NN) {
            int c = g_counts[idx];
            g_offsets[idx] = run;
            g_cursor[idx]  = run;
            g_invc[idx]    = 1.0f / (float)(c > 1 ? c : 1);
            run += c;
        }
    }
    if (t == 1023) g_offsets[NN] = part[1023];
}

__global__ void k_scatter(const void* __restrict__ ei) {
    int e = blockIdx.x * blockDim.x + threadIdx.x;
    if (e < NE) {
        int s = edge_at(ei, e);
        int d = edge_at(ei, NE + e);
        int pos = atomicAdd(&g_cursor[d], 1);
        g_esrc[pos] = s;
    }
}

// ---------------- layer-1 aggregation: agg[dst] = mean of x[src] -------------
// one warp per node, lane owns one float4 (128 dims = 32 * float4)
__global__ void k_agg1(const float* __restrict__ x) {
    int warp = (blockIdx.x * blockDim.x + threadIdx.x) >> 5;
    if (warp >= NN) return;
    int lane = threadIdx.x & 31;
    int beg = g_offsets[warp], end = g_offsets[warp + 1];
    const float4* __restrict__ x4 = (const float4*)x;
    float4 acc = make_float4(0.f, 0.f, 0.f, 0.f);
    int e = beg;
    for (; e + 1 < end; e += 2) {
        int s0 = g_esrc[e];
        int s1 = g_esrc[e + 1];
        float4 v0 = x4[(size_t)s0 * 32 + lane];
        float4 v1 = x4[(size_t)s1 * 32 + lane];
        acc.x += v0.x + v1.x;
        acc.y += v0.y + v1.y;
        acc.z += v0.z + v1.z;
        acc.w += v0.w + v1.w;
    }
    if (e < end) {
        int s0 = g_esrc[e];
        float4 v0 = x4[(size_t)s0 * 32 + lane];
        acc.x += v0.x; acc.y += v0.y; acc.z += v0.z; acc.w += v0.w;
    }
    float iv = g_invc[warp];
    float4 o = make_float4(acc.x * iv, acc.y * iv, acc.z * iv, acc.w * iv);
    ((float4*)g_agg)[(size_t)warp * 32 + lane] = o;
}

// ---------------- GEMM1: h = relu([agg|x] @ [W1_l;W1_r] + b1) ----------------
// BM=128, BN=128, BK=16, 256 threads, 8x8 strided microtile
__global__ void __launch_bounds__(256) k_gemm1(const float* __restrict__ x,
                                               const float* __restrict__ W1l,
                                               const float* __restrict__ W1r,
                                               const float* __restrict__ b1) {
    __shared__ float As[16][129];
    __shared__ float Bs[16][128];
    int bm = blockIdx.x * 128;
    int bn = blockIdx.y * 128;
    int tid = threadIdx.x;
    int tr = tid >> 4;        // 0..15
    int tc = tid & 15;        // 0..15

    float acc[8][8];
#pragma unroll
    for (int i = 0; i < 8; i++)
#pragma unroll
        for (int j = 0; j < 8; j++) acc[i][j] = 0.f;

    int arow = tid >> 1;           // 0..127
    int aq   = (tid & 1) * 8;      // 0 or 8
    int grow = bm + arow;
    bool rowok = grow < NN;

    int bkk = tid >> 4;            // 0..15
    int bn0 = (tid & 15) * 8;      // 0..120

    for (int k0 = 0; k0 < 256; k0 += 16) {
        // A tile (transposed into smem)
        float4 a0, a1;
        int k = k0 + aq;
        if (rowok) {
            const float* sbase = (k < 128)
                ? (g_agg + (size_t)grow * 128 + k)
                : (x + (size_t)grow * 128 + (k - 128));
            a0 = *(const float4*)sbase;
            a1 = *(const float4*)(sbase + 4);
        } else {
            a0 = make_float4(0.f, 0.f, 0.f, 0.f);
            a1 = a0;
        }
        As[aq + 0][arow] = a0.x; As[aq + 1][arow] = a0.y;
        As[aq + 2][arow] = a0.z; As[aq + 3][arow] = a0.w;
        As[aq + 4][arow] = a1.x; As[aq + 5][arow] = a1.y;
        As[aq + 6][arow] = a1.z; As[aq + 7][arow] = a1.w;

        // B tile
        int kb = k0 + bkk;
        const float* wb = (kb < 128)
            ? (W1l + (size_t)kb * 256 + bn + bn0)
            : (W1r + (size_t)(kb - 128) * 256 + bn + bn0);
        float4 b0 = *(const float4*)wb;
        float4 b1v = *(const float4*)(wb + 4);
        *(float4*)&Bs[bkk][bn0]     = b0;
        *(float4*)&Bs[bkk][bn0 + 4] = b1v;
        __syncthreads();

#pragma unroll
        for (int kk = 0; kk < 16; kk++) {
            float a[8], b[8];
#pragma unroll
            for (int i = 0; i < 8; i++) a[i] = As[kk][tr + i * 16];
#pragma unroll
            for (int j = 0; j < 8; j++) b[j] = Bs[kk][tc + j * 16];
#pragma unroll
            for (int i = 0; i < 8; i++)
#pragma unroll
                for (int j = 0; j < 8; j++) acc[i][j] += a[i] * b[j];
        }
        __syncthreads();
    }

#pragma unroll
    for (int i = 0; i < 8; i++) {
        int row = bm + i * 16 + tr;
        if (row < NN) {
#pragma unroll
            for (int j = 0; j < 8; j++) {
                int col = bn + j * 16 + tc;
                float v = acc[i][j] + b1[col];
                g_h[(size_t)row * 256 + col] = v > 0.f ? v : 0.f;
            }
        }
    }
}

// ---------------- GEMM2: p = h@W2_l ; r = h@W2_r + b2 ------------------------
// BM=128, BN=80 (p|r concatenated), BK=16, 256 threads, 8x5 microtile
__global__ void __launch_bounds__(256) k_gemm2(const float* __restrict__ W2l,
                                               const float* __restrict__ W2r,
                                               const float* __restrict__ b2) {
    __shared__ float As[16][129];
    __shared__ float Bs[16][80];
    int bm = blockIdx.x * 128;
    int tid = threadIdx.x;
    int tr = tid >> 4;
    int tc = tid & 15;

    float acc[8][5];
#pragma unroll
    for (int i = 0; i < 8; i++)
#pragma unroll
        for (int j = 0; j < 5; j++) acc[i][j] = 0.f;

    int arow = tid >> 1;
    int aq   = (tid & 1) * 8;
    int grow = bm + arow;
    bool rowok = grow < NN;

    for (int k0 = 0; k0 < 256; k0 += 16) {
        float4 a0, a1;
        if (rowok) {
            const float* sbase = g_h + (size_t)grow * 256 + k0 + aq;
            a0 = *(const float4*)sbase;
            a1 = *(const float4*)(sbase + 4);
        } else {
            a0 = make_float4(0.f, 0.f, 0.f, 0.f);
            a1 = a0;
        }
        As[aq + 0][arow] = a0.x; As[aq + 1][arow] = a0.y;
        As[aq + 2][arow] = a0.z; As[aq + 3][arow] = a0.w;
        As[aq + 4][arow] = a1.x; As[aq + 5][arow] = a1.y;
        As[aq + 6][arow] = a1.z; As[aq + 7][arow] = a1.w;

        // B tile: 16x80 = 1280 elems, 5 per thread
#pragma unroll
        for (int i = 0; i < 5; i++) {
            int id = tid + i * 256;
            int kk = id / 80;
            int n  = id % 80;
            float v = (n < 40) ? W2l[(size_t)(k0 + kk) * 40 + n]
                               : W2r[(size_t)(k0 + kk) * 40 + (n - 40)];
            Bs[kk][n] = v;
        }
        __syncthreads();

#pragma unroll
        for (int kk = 0; kk < 16; kk++) {
            float a[8], b[5];
#pragma unroll
            for (int i = 0; i < 8; i++) a[i] = As[kk][tr + i * 16];
#pragma unroll
            for (int j = 0; j < 5; j++) b[j] = Bs[kk][tc + j * 16];
#pragma unroll
            for (int i = 0; i < 8; i++)
#pragma unroll
                for (int j = 0; j < 5; j++) acc[i][j] += a[i] * b[j];
        }
        __syncthreads();
    }

#pragma unroll
    for (int i = 0; i < 8; i++) {
        int row = bm + i * 16 + tr;
        if (row < NN) {
#pragma unroll
            for (int j = 0; j < 5; j++) {
                int col = j * 16 + tc;
                if (col < 40) {
                    g_p[(size_t)row * 40 + col] = acc[i][j];
                } else {
                    g_r[(size_t)row * 40 + (col - 40)] = acc[i][j] + b2[col - 40];
                }
            }
        }
    }
}

// ---------------- layer-2 aggregation + residual + log_softmax ---------------
// one warp per node; lane owns cols {lane, lane+32(if <40)}
__global__ void k_agg2_lsm(float* __restrict__ out) {
    int warp = (blockIdx.x * blockDim.x + threadIdx.x) >> 5;
    if (warp >= NN) return;
    int lane = threadIdx.x & 31;
    int beg = g_offsets[warp], end = g_offsets[warp + 1];
    bool h1 = lane < 8;
    float a0 = 0.f, a1 = 0.f;
    for (int e = beg; e < end; e++) {
        int s = g_esrc[e];
        const float* ps = g_p + (size_t)s * 40;
        a0 += ps[lane];
        if (h1) a1 += ps[32 + lane];
    }
    float iv = g_invc[warp];
    float v0 = a0 * iv + g_r[(size_t)warp * 40 + lane];
    float v1 = h1 ? (a1 * iv + g_r[(size_t)warp * 40 + 32 + lane]) : -3.0e38f;

    float m = fmaxf(v0, v1);
#pragma unroll
    for (int off = 16; off; off >>= 1)
        m = fmaxf(m, __shfl_xor_sync(0xffffffffu, m, off));
    float ssum = expf(v0 - m) + (h1 ? expf(v1 - m) : 0.f);
#pragma unroll
    for (int off = 16; off; off >>= 1)
        ssum += __shfl_xor_sync(0xffffffffu, ssum, off);
    float lse = m + logf(ssum);

    out[(size_t)warp * 40 + lane] = v0 - lse;
    if (h1) out[(size_t)warp * 40 + 32 + lane] = v1 - lse;
}

// ---------------- launch -----------------------------------------------------
extern "C" void kernel_launch(void* const* d_in, const int* in_sizes, int n_in,
                              void* d_out, int out_size) {
    const float* x   = (const float*)d_in[0];
    const void*  ei  = d_in[1];
    const float* W1l = (const float*)d_in[2];
    const float* W1r = (const float*)d_in[3];
    const float* b1  = (const float*)d_in[4];
    const float* W2l = (const float*)d_in[5];
    const float* W2r = (const float*)d_in[6];
    const float* b2  = (const float*)d_in[7];
    float* out = (float*)d_out;

    k_detect<<<1, 1024>>>((const int*)ei);
    k_zero_counts<<<(NN + 255) / 256, 256>>>();
    k_count<<<(NE + 255) / 256, 256>>>(ei);
    k_scan<<<1, 1024>>>();
    k_scatter<<<(NE + 255) / 256, 256>>>(ei);
    k_agg1<<<(NN + 7) / 8, 256>>>(x);
    dim3 g1((NN + 127) / 128, 2);
    k_gemm1<<<g1, 256>>>(x, W1l, W1r, b1);
    k_gemm2<<<(NN + 127) / 128, 256>>>(W2l, W2r, b2);
    k_agg2_lsm<<<(NN + 7) / 8, 256>>>(out);
}

// round 3
// speedup vs baseline: 1.3194x; 1.3194x over previous
#include <cuda_runtime.h>
#include <math.h>

#define NN   50000
#define NE   800000
#define IND  128
#define HID  256
#define OUTD 40
#define NB   ((NN + 255) / 256)   // 196 scan blocks

// ---------------- scratch ----------------------------------------------------
__device__ int   g_is64;
__device__ int   g_counts[NN];
__device__ int   g_offsets[NN + 1];
__device__ int   g_cursor[NN];
__device__ int   g_esrc[NE];
__device__ float g_invc[NN];
__device__ int   g_bsum[NB];
__device__ int   g_boff[NB];
__device__ __align__(16) float g_agg[(size_t)NN * IND];
__device__ __align__(16) float g_h[(size_t)NN * HID];
__device__ __align__(16) float g_p[(size_t)NN * OUTD];
__device__ __align__(16) float g_r[(size_t)NN * OUTD];

// ---------------- f32x2 fma --------------------------------------------------
__device__ __forceinline__ void ffma2(float2& c, float2 a, float2 b) {
    unsigned long long ua = *reinterpret_cast<unsigned long long*>(&a);
    unsigned long long ub = *reinterpret_cast<unsigned long long*>(&b);
    unsigned long long uc = *reinterpret_cast<unsigned long long*>(&c);
    asm("fma.rn.f32x2 %0, %1, %2, %0;" : "+l"(uc) : "l"(ua), "l"(ub));
    c = *reinterpret_cast<float2*>(&uc);
}

// ---------------- edge dtype detection --------------------------------------
__global__ void k_detect(const int* __restrict__ ei32) {
    __shared__ int bad;
    if (threadIdx.x == 0) bad = 0;
    __syncthreads();
    if (ei32[2 * threadIdx.x + 1] != 0) atomicOr(&bad, 1);
    __syncthreads();
    if (threadIdx.x == 0) g_is64 = bad ? 0 : 1;
}

__device__ __forceinline__ int edge_at(const void* ei, int idx) {
    if (g_is64) return (int)((const long long*)ei)[idx];
    return ((const int*)ei)[idx];
}

// ---------------- CSR build --------------------------------------------------
__global__ void k_zero_counts() {
    int i = blockIdx.x * blockDim.x + threadIdx.x;
    if (i < NN) g_counts[i] = 0;
}

__global__ void k_count(const void* __restrict__ ei) {
    int e = blockIdx.x * blockDim.x + threadIdx.x;
    if (e < NE) atomicAdd(&g_counts[edge_at(ei, NE + e)], 1);
}

// block-level exclusive scan helper (256 threads)
__device__ __forceinline__ int block_excl_scan(int c, int t) {
    int lane = t & 31, w = t >> 5;
    int v = c;
#pragma unroll
    for (int off = 1; off < 32; off <<= 1) {
        int n = __shfl_up_sync(0xffffffffu, v, off);
        if (lane >= off) v += n;
    }
    __shared__ int ws[8];
    if (lane == 31) ws[w] = v;
    __syncthreads();
    if (w == 0 && lane < 8) {
        int s = ws[lane];
#pragma unroll
        for (int off = 1; off < 8; off <<= 1) {
            int n = __shfl_up_sync(0x000000ffu, s, off);
            if (lane >= off) s += n;
        }
        ws[lane] = s;
    }
    __syncthreads();
    return v - c + (w > 0 ? ws[w - 1] : 0);
}

// scan stage A: per-block sums of counts
__global__ void k_scanA() {
    int i = blockIdx.x * 256 + threadIdx.x;
    int c = (i < NN) ? g_counts[i] : 0;
    int lane = threadIdx.x & 31, w = threadIdx.x >> 5;
#pragma unroll
    for (int off = 16; off; off >>= 1) c += __shfl_xor_sync(0xffffffffu, c, off);
    __shared__ int ws[8];
    if (lane == 0) ws[w] = c;
    __syncthreads();
    if (threadIdx.x == 0) {
        int s = 0;
#pragma unroll
        for (int k = 0; k < 8; k++) s += ws[k];
        g_bsum[blockIdx.x] = s;
    }
}

// scan stage B: exclusive scan of NB block sums (1 block)
__global__ void k_scanB() {
    int t = threadIdx.x;
    int v = (t < NB) ? g_bsum[t] : 0;
    int e = block_excl_scan(v, t);
    if (t < NB) g_boff[t] = e;
    if (t == 0) g_offsets[NN] = NE;
}

// scan stage C: final offsets
__global__ void k_scanC() {
    int i = blockIdx.x * 256 + threadIdx.x;
    int c = (i < NN) ? g_counts[i] : 0;
    int e = block_excl_scan(c, threadIdx.x);
    if (i < NN) {
        int off = g_boff[blockIdx.x] + e;
        g_offsets[i] = off;
        g_cursor[i]  = off;
        g_invc[i]    = 1.0f / (float)(c > 1 ? c : 1);
    }
}

__global__ void k_scatter(const void* __restrict__ ei) {
    int e = blockIdx.x * blockDim.x + threadIdx.x;
    if (e < NE) {
        int s = edge_at(ei, e);
        int d = edge_at(ei, NE + e);
        g_esrc[atomicAdd(&g_cursor[d], 1)] = s;
    }
}

// ---------------- layer-1 aggregation ----------------------------------------
__global__ void k_agg1(const float* __restrict__ x) {
    int warp = (blockIdx.x * blockDim.x + threadIdx.x) >> 5;
    if (warp >= NN) return;
    int lane = threadIdx.x & 31;
    int beg = g_offsets[warp], end = g_offsets[warp + 1];
    const float4* __restrict__ x4 = (const float4*)x;
    float4 acc = make_float4(0.f, 0.f, 0.f, 0.f);
    int e = beg;
    for (; e + 1 < end; e += 2) {
        int s0 = g_esrc[e];
        int s1 = g_esrc[e + 1];
        float4 v0 = x4[(size_t)s0 * 32 + lane];
        float4 v1 = x4[(size_t)s1 * 32 + lane];
        acc.x += v0.x + v1.x; acc.y += v0.y + v1.y;
        acc.z += v0.z + v1.z; acc.w += v0.w + v1.w;
    }
    if (e < end) {
        int s0 = g_esrc[e];
        float4 v0 = x4[(size_t)s0 * 32 + lane];
        acc.x += v0.x; acc.y += v0.y; acc.z += v0.z; acc.w += v0.w;
    }
    float iv = g_invc[warp];
    ((float4*)g_agg)[(size_t)warp * 32 + lane] =
        make_float4(acc.x * iv, acc.y * iv, acc.z * iv, acc.w * iv);
}

// ---------------- GEMM1: h = relu([agg|x] @ [W1_l;W1_r] + b1) ----------------
// BM=128, BN=128, BK=16, 256 threads; FFMA2 microtile 8 rows x 4 col-pairs
__global__ void __launch_bounds__(256) k_gemm1(const float* __restrict__ x,
                                               const float* __restrict__ W1l,
                                               const float* __restrict__ W1r,
                                               const float* __restrict__ b1) {
    __shared__ float Asd[16][258];   // duplicated pairs: [kk][2*row]
    __shared__ float Bs[16][128];
    int bm = blockIdx.x * 128;
    int bn = blockIdx.y * 128;
    int tid = threadIdx.x;
    int tr = tid >> 4;        // rows tr + 16*i
    int tc = tid & 15;        // col pairs 2*tc + 32*j

    float2 acc[8][4];
#pragma unroll
    for (int i = 0; i < 8; i++)
#pragma unroll
        for (int j = 0; j < 4; j++) acc[i][j] = make_float2(0.f, 0.f);

    int arow = tid >> 1;
    int aq   = (tid & 1) * 8;
    int grow = bm + arow;
    bool rowok = grow < NN;

    int bkk = tid >> 4;
    int bn0 = (tid & 15) * 8;

    for (int k0 = 0; k0 < 256; k0 += 16) {
        float4 a0, a1;
        int k = k0 + aq;
        if (rowok) {
            const float* sbase = (k < 128)
                ? (g_agg + (size_t)grow * 128 + k)
                : (x + (size_t)grow * 128 + (k - 128));
            a0 = *(const float4*)sbase;
            a1 = *(const float4*)(sbase + 4);
        } else {
            a0 = make_float4(0.f, 0.f, 0.f, 0.f);
            a1 = a0;
        }
        float av[8] = {a0.x, a0.y, a0.z, a0.w, a1.x, a1.y, a1.z, a1.w};
#pragma unroll
        for (int q = 0; q < 8; q++)
            *(float2*)&Asd[aq + q][2 * arow] = make_float2(av[q], av[q]);

        int kb = k0 + bkk;
        const float* wb = (kb < 128)
            ? (W1l + (size_t)kb * 256 + bn + bn0)
            : (W1r + (size_t)(kb - 128) * 256 + bn + bn0);
        *(float4*)&Bs[bkk][bn0]     = *(const float4*)wb;
        *(float4*)&Bs[bkk][bn0 + 4] = *(const float4*)(wb + 4);
        __syncthreads();

#pragma unroll
        for (int kk = 0; kk < 16; kk++) {
            float2 a2[8], b2[4];
#pragma unroll
            for (int i = 0; i < 8; i++) a2[i] = *(float2*)&Asd[kk][2 * (tr + 16 * i)];
#pragma unroll
            for (int j = 0; j < 4; j++) b2[j] = *(float2*)&Bs[kk][2 * tc + 32 * j];
#pragma unroll
            for (int i = 0; i < 8; i++)
#pragma unroll
                for (int j = 0; j < 4; j++) ffma2(acc[i][j], a2[i], b2[j]);
        }
        __syncthreads();
    }

#pragma unroll
    for (int i = 0; i < 8; i++) {
        int row = bm + tr + 16 * i;
        if (row < NN) {
#pragma unroll
            for (int j = 0; j < 4; j++) {
                int col = bn + 2 * tc + 32 * j;
                float2 v = acc[i][j];
                v.x += b1[col];
                v.y += b1[col + 1];
                v.x = v.x > 0.f ? v.x : 0.f;
                v.y = v.y > 0.f ? v.y : 0.f;
                *(float2*)&g_h[(size_t)row * 256 + col] = v;
            }
        }
    }
}

// ---------------- GEMM2: [p|r] = h @ [W2_l|W2_r] -----------------------------
// BM=128, BN=80, BK=16, 256 threads; microtile 4 rows x 5 col-pairs
__global__ void __launch_bounds__(256) k_gemm2(const float* __restrict__ W2l,
                                               const float* __restrict__ W2r,
                                               const float* __restrict__ b2) {
    __shared__ float Asd[16][258];
    __shared__ float Bs[16][80];
    int bm = blockIdx.x * 128;
    int tid = threadIdx.x;
    int tr = tid >> 3;        // 0..31, rows tr + 32*i (i=0..3)
    int tc = tid & 7;         // col pairs 2*tc + 16*j (j=0..4)

    float2 acc[4][5];
#pragma unroll
    for (int i = 0; i < 4; i++)
#pragma unroll
        for (int j = 0; j < 5; j++) acc[i][j] = make_float2(0.f, 0.f);

    int arow = tid >> 1;
    int aq   = (tid & 1) * 8;
    int grow = bm + arow;
    bool rowok = grow < NN;

    for (int k0 = 0; k0 < 256; k0 += 16) {
        float4 a0, a1;
        if (rowok) {
            const float* sbase = g_h + (size_t)grow * 256 + k0 + aq;
            a0 = *(const float4*)sbase;
            a1 = *(const float4*)(sbase + 4);
        } else {
            a0 = make_float4(0.f, 0.f, 0.f, 0.f);
            a1 = a0;
        }
        float av[8] = {a0.x, a0.y, a0.z, a0.w, a1.x, a1.y, a1.z, a1.w};
#pragma unroll
        for (int q = 0; q < 8; q++)
            *(float2*)&Asd[aq + q][2 * arow] = make_float2(av[q], av[q]);

#pragma unroll
        for (int i = 0; i < 5; i++) {
            int id = tid + i * 256;
            int kk = id / 80;
            int n  = id % 80;
            Bs[kk][n] = (n < 40) ? W2l[(size_t)(k0 + kk) * 40 + n]
                                 : W2r[(size_t)(k0 + kk) * 40 + (n - 40)];
        }
        __syncthreads();

#pragma unroll
        for (int kk = 0; kk < 16; kk++) {
            float2 a2[4], b2[5];
#pragma unroll
            for (int i = 0; i < 4; i++) a2[i] = *(float2*)&Asd[kk][2 * (tr + 32 * i)];
#pragma unroll
            for (int j = 0; j < 5; j++) b2[j] = *(float2*)&Bs[kk][2 * tc + 16 * j];
#pragma unroll
            for (int i = 0; i < 4; i++)
#pragma unroll
                for (int j = 0; j < 5; j++) ffma2(acc[i][j], a2[i], b2[j]);
        }
        __syncthreads();
    }

#pragma unroll
    for (int i = 0; i < 4; i++) {
        int row = bm + tr + 32 * i;
        if (row < NN) {
#pragma unroll
            for (int j = 0; j < 5; j++) {
                int col = 2 * tc + 16 * j;       // even, never straddles 40
                float2 v = acc[i][j];
                if (col < 40) {
                    *(float2*)&g_p[(size_t)row * 40 + col] = v;
                } else {
                    v.x += b2[col - 40];
                    v.y += b2[col - 39];
                    *(float2*)&g_r[(size_t)row * 40 + (col - 40)] = v;
                }
            }
        }
    }
}

// ---------------- layer-2 aggregation + log_softmax --------------------------
__global__ void k_agg2_lsm(float* __restrict__ out) {
    int warp = (blockIdx.x * blockDim.x + threadIdx.x) >> 5;
    if (warp >= NN) return;
    int lane = threadIdx.x & 31;
    int beg = g_offsets[warp], end = g_offsets[warp + 1];
    bool h1 = lane < 8;
    float a0 = 0.f, a1 = 0.f;
    for (int e = beg; e < end; e++) {
        int s = g_esrc[e];
        const float* ps = g_p + (size_t)s * 40;
        a0 += ps[lane];
        if (h1) a1 += ps[32 + lane];
    }
    float iv = g_invc[warp];
    float v0 = a0 * iv + g_r[(size_t)warp * 40 + lane];
    float v1 = h1 ? (a1 * iv + g_r[(size_t)warp * 40 + 32 + lane]) : -3.0e38f;

    float m = fmaxf(v0, v1);
#pragma unroll
    for (int off = 16; off; off >>= 1)
        m = fmaxf(m, __shfl_xor_sync(0xffffffffu, m, off));
    float ssum = expf(v0 - m) + (h1 ? expf(v1 - m) : 0.f);
#pragma unroll
    for (int off = 16; off; off >>= 1)
        ssum += __shfl_xor_sync(0xffffffffu, ssum, off);
    float lse = m + logf(ssum);

    out[(size_t)warp * 40 + lane] = v0 - lse;
    if (h1) out[(size_t)warp * 40 + 32 + lane] = v1 - lse;
}

// ---------------- launch -----------------------------------------------------
extern "C" void kernel_launch(void* const* d_in, const int* in_sizes, int n_in,
                              void* d_out, int out_size) {
    const float* x   = (const float*)d_in[0];
    const void*  ei  = d_in[1];
    const float* W1l = (const float*)d_in[2];
    const float* W1r = (const float*)d_in[3];
    const float* b1  = (const float*)d_in[4];
    const float* W2l = (const float*)d_in[5];
    const float* W2r = (const float*)d_in[6];
    const float* b2  = (const float*)d_in[7];
    float* out = (float*)d_out;

    k_detect<<<1, 1024>>>((const int*)ei);
    k_zero_counts<<<(NN + 255) / 256, 256>>>();
    k_count<<<(NE + 255) / 256, 256>>>(ei);
    k_scanA<<<NB, 256>>>();
    k_scanB<<<1, 256>>>();
    k_scanC<<<NB, 256>>>();
    k_scatter<<<(NE + 255) / 256, 256>>>(ei);
    k_agg1<<<(NN + 7) / 8, 256>>>(x);
    dim3 g1((NN + 127) / 128, 2);
    k_gemm1<<<g1, 256>>>(x, W1l, W1r, b1);
    k_gemm2<<<(NN + 127) / 128, 256>>>(W2l, W2r, b2);
    k_agg2_lsm<<<(NN + 7) / 8, 256>>>(out);
}

// round 5
// speedup vs baseline: 1.8318x; 1.3883x over previous
#include <cuda_runtime.h>
#include <cuda_bf16.h>
#include <math.h>
#include <cstdint>

#define NN   50000
#define NE   800000
#define IND  128
#define HID  256
#define OUTD 40
#define NB   ((NN + 255) / 256)   // 196 scan blocks

// ---------------- scratch ----------------------------------------------------
__device__ int   g_is64;
__device__ int   g_counts[NN];
__device__ int   g_offsets[NN + 1];
__device__ int   g_cursor[NN];
__device__ int   g_esrc[NE];
__device__ float g_invc[NN];
__device__ int   g_bsum[NB];
__device__ int   g_boff[NB];
__device__ __align__(16) __nv_bfloat16 g_a_hi[(size_t)NN * HID];  // [agg|x] hi
__device__ __align__(16) __nv_bfloat16 g_a_lo[(size_t)NN * HID];  // [agg|x] lo
__device__ __align__(16) __nv_bfloat16 g_w1hi[(size_t)HID * HID]; // W1^T hi [n][k]
__device__ __align__(16) __nv_bfloat16 g_w1lo[(size_t)HID * HID]; // W1^T lo [n][k]
__device__ __align__(16) float g_h[(size_t)NN * HID];
__device__ __align__(16) float g_p[(size_t)NN * OUTD];
__device__ __align__(16) float g_r[(size_t)NN * OUTD];

// ---------------- helpers ----------------------------------------------------
__device__ __forceinline__ uint32_t smem_u32(const void* p) {
    uint32_t a;
    asm("{ .reg .u64 t; cvta.to.shared.u64 t, %1; cvt.u32.u64 %0, t; }"
        : "=r"(a) : "l"(p));
    return a;
}

#define SW128(o) ((o) ^ (((o) >> 3) & 0x70))

#define LDSM4(R, ADDR)                                                           \
    asm volatile("ldmatrix.sync.aligned.m8n8.x4.shared.b16 {%0,%1,%2,%3}, [%4];" \
        : "=r"((R)[0]), "=r"((R)[1]), "=r"((R)[2]), "=r"((R)[3]) : "r"(ADDR))

__device__ __forceinline__ void mma16816(float* c, const uint32_t* a,
                                         uint32_t b0, uint32_t b1) {
    asm volatile(
        "mma.sync.aligned.m16n8k16.row.col.f32.bf16.bf16.f32 "
        "{%0,%1,%2,%3}, {%4,%5,%6,%7}, {%8,%9}, {%0,%1,%2,%3};"
        : "+f"(c[0]), "+f"(c[1]), "+f"(c[2]), "+f"(c[3])
        : "r"(a[0]), "r"(a[1]), "r"(a[2]), "r"(a[3]), "r"(b0), "r"(b1));
}

// ---------------- f32x2 fma --------------------------------------------------
__device__ __forceinline__ void ffma2(float2& c, float2 a, float2 b) {
    unsigned long long ua = *reinterpret_cast<unsigned long long*>(&a);
    unsigned long long ub = *reinterpret_cast<unsigned long long*>(&b);
    unsigned long long uc = *reinterpret_cast<unsigned long long*>(&c);
    asm("fma.rn.f32x2 %0, %1, %2, %0;" : "+l"(uc) : "l"(ua), "l"(ub));
    c = *reinterpret_cast<float2*>(&uc);
}

// ---------------- edge dtype detection --------------------------------------
__global__ void k_detect(const int* __restrict__ ei32) {
    __shared__ int bad;
    if (threadIdx.x == 0) bad = 0;
    __syncthreads();
    if (ei32[2 * threadIdx.x + 1] != 0) atomicOr(&bad, 1);
    __syncthreads();
    if (threadIdx.x == 0) g_is64 = bad ? 0 : 1;
}

__device__ __forceinline__ int edge_at(const void* ei, int idx) {
    if (g_is64) return (int)((const long long*)ei)[idx];
    return ((const int*)ei)[idx];
}

// ---------------- CSR build --------------------------------------------------
__global__ void k_zero_counts() {
    int i = blockIdx.x * blockDim.x + threadIdx.x;
    if (i < NN) g_counts[i] = 0;
}

__global__ void k_count(const void* __restrict__ ei) {
    int e = blockIdx.x * blockDim.x + threadIdx.x;
    if (e < NE) atomicAdd(&g_counts[edge_at(ei, NE + e)], 1);
}

__device__ __forceinline__ int block_excl_scan(int c, int t) {
    int lane = t & 31, w = t >> 5;
    int v = c;
#pragma unroll
    for (int off = 1; off < 32; off <<= 1) {
        int n = __shfl_up_sync(0xffffffffu, v, off);
        if (lane >= off) v += n;
    }
    __shared__ int ws[8];
    if (lane == 31) ws[w] = v;
    __syncthreads();
    if (w == 0 && lane < 8) {
        int s = ws[lane];
#pragma unroll
        for (int off = 1; off < 8; off <<= 1) {
            int n = __shfl_up_sync(0x000000ffu, s, off);
            if (lane >= off) s += n;
        }
        ws[lane] = s;
    }
    __syncthreads();
    return v - c + (w > 0 ? ws[w - 1] : 0);
}

__global__ void k_scanA() {
    int i = blockIdx.x * 256 + threadIdx.x;
    int c = (i < NN) ? g_counts[i] : 0;
    int lane = threadIdx.x & 31, w = threadIdx.x >> 5;
#pragma unroll
    for (int off = 16; off; off >>= 1) c += __shfl_xor_sync(0xffffffffu, c, off);
    __shared__ int ws[8];
    if (lane == 0) ws[w] = c;
    __syncthreads();
    if (threadIdx.x == 0) {
        int s = 0;
#pragma unroll
        for (int k = 0; k < 8; k++) s += ws[k];
        g_bsum[blockIdx.x] = s;
    }
}

__global__ void k_scanB() {
    int t = threadIdx.x;
    int v = (t < NB) ? g_bsum[t] : 0;
    int e = block_excl_scan(v, t);
    if (t < NB) g_boff[t] = e;
    if (t == 0) g_offsets[NN] = NE;
}

__global__ void k_scanC() {
    int i = blockIdx.x * 256 + threadIdx.x;
    int c = (i < NN) ? g_counts[i] : 0;
    int e = block_excl_scan(c, threadIdx.x);
    if (i < NN) {
        int off = g_boff[blockIdx.x] + e;
        g_offsets[i] = off;
        g_cursor[i]  = off;
        g_invc[i]    = 1.0f / (float)(c > 1 ? c : 1);
    }
}

__global__ void k_scatter(const void* __restrict__ ei) {
    int e = blockIdx.x * blockDim.x + threadIdx.x;
    if (e < NE) {
        int s = edge_at(ei, e);
        int d = edge_at(ei, NE + e);
        g_esrc[atomicAdd(&g_cursor[d], 1)] = s;
    }
}

// ---------------- bf16 split helpers -----------------------------------------
__device__ __forceinline__ void split4(float4 v, uint2& hi, uint2& lo) {
    __nv_bfloat16 h0 = __float2bfloat16(v.x);
    __nv_bfloat16 h1 = __float2bfloat16(v.y);
    __nv_bfloat16 h2 = __float2bfloat16(v.z);
    __nv_bfloat16 h3 = __float2bfloat16(v.w);
    __nv_bfloat16 l0 = __float2bfloat16(v.x - __bfloat162float(h0));
    __nv_bfloat16 l1 = __float2bfloat16(v.y - __bfloat162float(h1));
    __nv_bfloat16 l2 = __float2bfloat16(v.z - __bfloat162float(h2));
    __nv_bfloat16 l3 = __float2bfloat16(v.w - __bfloat162float(h3));
    unsigned short uh0 = __bfloat16_as_ushort(h0), uh1 = __bfloat16_as_ushort(h1);
    unsigned short uh2 = __bfloat16_as_ushort(h2), uh3 = __bfloat16_as_ushort(h3);
    unsigned short ul0 = __bfloat16_as_ushort(l0), ul1 = __bfloat16_as_ushort(l1);
    unsigned short ul2 = __bfloat16_as_ushort(l2), ul3 = __bfloat16_as_ushort(l3);
    hi.x = (uint32_t)uh0 | ((uint32_t)uh1 << 16);
    hi.y = (uint32_t)uh2 | ((uint32_t)uh3 << 16);
    lo.x = (uint32_t)ul0 | ((uint32_t)ul1 << 16);
    lo.y = (uint32_t)ul2 | ((uint32_t)ul3 << 16);
}

// ---------------- W1 prep: transpose + bf16-split into [n][k] ----------------
__global__ void k_w1prep(const float* __restrict__ W1l,
                         const float* __restrict__ W1r) {
    int idx = blockIdx.x * 256 + threadIdx.x;   // 65536
    int n = idx >> 8, k = idx & 255;
    float w = (k < 128) ? W1l[(size_t)k * 256 + n]
                        : W1r[(size_t)(k - 128) * 256 + n];
    __nv_bfloat16 h = __float2bfloat16(w);
    __nv_bfloat16 l = __float2bfloat16(w - __bfloat162float(h));
    g_w1hi[(size_t)n * 256 + k] = h;
    g_w1lo[(size_t)n * 256 + k] = l;
}

// ---------------- x conversion into cols 128..255 of A -----------------------
__global__ void k_xconv(const float* __restrict__ x) {
    int idx = blockIdx.x * 256 + threadIdx.x;
    if (idx >= NN * 32) return;
    int row = idx >> 5, c4 = idx & 31;
    float4 v = ((const float4*)x)[(size_t)row * 32 + c4];
    uint2 hi, lo;
    split4(v, hi, lo);
    *(uint2*)&g_a_hi[(size_t)row * 256 + 128 + c4 * 4] = hi;
    *(uint2*)&g_a_lo[(size_t)row * 256 + 128 + c4 * 4] = lo;
}

// ---------------- layer-1 aggregation (bf16 hi/lo cols 0..127) ---------------
__global__ void k_agg1(const float* __restrict__ x) {
    int warp = (blockIdx.x * blockDim.x + threadIdx.x) >> 5;
    if (warp >= NN) return;
    int lane = threadIdx.x & 31;
    int beg = g_offsets[warp], end = g_offsets[warp + 1];
    const float4* __restrict__ x4 = (const float4*)x;
    float4 acc = make_float4(0.f, 0.f, 0.f, 0.f);
    int e = beg;
    for (; e + 1 < end; e += 2) {
        int s0 = g_esrc[e];
        int s1 = g_esrc[e + 1];
        float4 v0 = x4[(size_t)s0 * 32 + lane];
        float4 v1 = x4[(size_t)s1 * 32 + lane];
        acc.x += v0.x + v1.x; acc.y += v0.y + v1.y;
        acc.z += v0.z + v1.z; acc.w += v0.w + v1.w;
    }
    if (e < end) {
        int s0 = g_esrc[e];
        float4 v0 = x4[(size_t)s0 * 32 + lane];
        acc.x += v0.x; acc.y += v0.y; acc.z += v0.z; acc.w += v0.w;
    }
    float iv = g_invc[warp];
    float4 o = make_float4(acc.x * iv, acc.y * iv, acc.z * iv, acc.w * iv);
    uint2 hi, lo;
    split4(o, hi, lo);
    *(uint2*)&g_a_hi[(size_t)warp * 256 + lane * 4] = hi;
    *(uint2*)&g_a_lo[(size_t)warp * 256 + lane * 4] = lo;
}

// ---------------- GEMM1 via mma.sync (bf16 3-pass split) ---------------------
// h = relu(A @ W1^T + b1).  A [NN][256] hi/lo, B = W1^T [256 n][256 k] hi/lo.
// Block tile 128x128, grid (391, 2); 8 warps, warp tile 32x64.
#define GA_H 0
#define GA_L 16384
#define GB_H 32768
#define GB_L 49152
#define DYN_SMEM1 65536

__global__ void __launch_bounds__(256, 1) k_gemm1_mma(const float* __restrict__ b1) {
    extern __shared__ char dsm[];
    int tid = threadIdx.x;
    int wid = tid >> 5;
    int lane = tid & 31;
    int bm = blockIdx.x * 128;
    int bn = blockIdx.y * 128;
    uint32_t dynb = smem_u32(dsm);

    int warp_m = (wid & 3) * 32;
    int warp_n = (wid >> 2) * 64;

    // ldmatrix source offsets (fixed across K chunks; swizzled)
    uint32_t offA[2][4], offB[4][4];
    {
        int mat = lane >> 3, rr = lane & 7;
#pragma unroll
        for (int i = 0; i < 2; i++)
#pragma unroll
            for (int j = 0; j < 4; j++) {
                int row = warp_m + i * 16 + ((mat & 1) << 3) + rr;
                int kb  = j * 16 + ((mat >> 1) << 3);
                offA[i][j] = SW128(row * 128 + kb * 2);
            }
#pragma unroll
        for (int q = 0; q < 4; q++)
#pragma unroll
            for (int j = 0; j < 4; j++) {
                int n  = warp_n + q * 16 + ((mat & 2) << 2) + rr;
                int kb = j * 16 + ((mat & 1) << 3);
                offB[q][j] = SW128(n * 128 + kb * 2);
            }
    }

    float acc[2][8][4];
#pragma unroll
    for (int i = 0; i < 2; i++)
#pragma unroll
        for (int jn = 0; jn < 8; jn++)
#pragma unroll
            for (int t = 0; t < 4; t++) acc[i][jn][t] = 0.f;

    for (int k0 = 0; k0 < 256; k0 += 64) {
        // stage A hi/lo (128x64 each)
#pragma unroll
        for (int it = 0; it < 4; it++) {
            int idx = tid + it * 256;
            int row = idx >> 3, seg = idx & 7;
            int grow = bm + row;
            int4 vh = make_int4(0, 0, 0, 0), vl = make_int4(0, 0, 0, 0);
            if (grow < NN) {
                size_t boff = ((size_t)grow * 256 + k0 + seg * 8) * 2;
                vh = *(const int4*)((const char*)g_a_hi + boff);
                vl = *(const int4*)((const char*)g_a_lo + boff);
            }
            int so = SW128(row * 128 + seg * 16);
            *(int4*)(dsm + GA_H + so) = vh;
            *(int4*)(dsm + GA_L + so) = vl;
        }
        // stage B hi/lo (rows bn..bn+127 of W1^T)
#pragma unroll
        for (int it = 0; it < 4; it++) {
            int idx = tid + it * 256;
            int row = idx >> 3, seg = idx & 7;
            size_t boff = ((size_t)(bn + row) * 256 + k0 + seg * 8) * 2;
            int4 vh = *(const int4*)((const char*)g_w1hi + boff);
            int4 vl = *(const int4*)((const char*)g_w1lo + boff);
            int so = SW128(row * 128 + seg * 16);
            *(int4*)(dsm + GB_H + so) = vh;
            *(int4*)(dsm + GB_L + so) = vl;
        }
        __syncthreads();

#pragma unroll
        for (int j = 0; j < 4; j++) {
            uint32_t ah[2][4], al[2][4], bh[4][4], bl[4][4];
#pragma unroll
            for (int i = 0; i < 2; i++) {
                LDSM4(ah[i], dynb + GA_H + offA[i][j]);
                LDSM4(al[i], dynb + GA_L + offA[i][j]);
            }
#pragma unroll
            for (int q = 0; q < 4; q++) {
                LDSM4(bh[q], dynb + GB_H + offB[q][j]);
                LDSM4(bl[q], dynb + GB_L + offB[q][j]);
            }
#pragma unroll
            for (int i = 0; i < 2; i++)
#pragma unroll
                for (int jn = 0; jn < 8; jn++) {
                    int q = jn >> 1, hsel = (jn & 1) * 2;
                    uint32_t bh0 = bh[q][hsel], bh1 = bh[q][hsel + 1];
                    uint32_t bl0 = bl[q][hsel], bl1 = bl[q][hsel + 1];
                    mma16816(acc[i][jn], ah[i], bh0, bh1);
                    mma16816(acc[i][jn], ah[i], bl0, bl1);
                    mma16816(acc[i][jn], al[i], bh0, bh1);
                }
        }
        __syncthreads();
    }

    // epilogue: c0,c1 -> (row, col..col+1); c2,c3 -> (row+8, ...)
    int r0 = bm + warp_m + (lane >> 2);
    int c0 = bn + warp_n + 2 * (lane & 3);
#pragma unroll
    for (int i = 0; i < 2; i++) {
        int row = r0 + i * 16;
#pragma unroll
        for (int jn = 0; jn < 8; jn++) {
            int col = c0 + jn * 8;
            float bx = b1[col], by = b1[col + 1];
            if (row < NN) {
                float2 v;
                v.x = acc[i][jn][0] + bx;
                v.y = acc[i][jn][1] + by;
                v.x = v.x > 0.f ? v.x : 0.f;
                v.y = v.y > 0.f ? v.y : 0.f;
                *(float2*)&g_h[(size_t)row * 256 + col] = v;
            }
            if (row + 8 < NN) {
                float2 v;
                v.x = acc[i][jn][2] + bx;
                v.y = acc[i][jn][3] + by;
                v.x = v.x > 0.f ? v.x : 0.f;
                v.y = v.y > 0.f ? v.y : 0.f;
                *(float2*)&g_h[(size_t)(row + 8) * 256 + col] = v;
            }
        }
    }
}

// ---------------- GEMM2: [p|r] = h @ [W2_l|W2_r] (FFMA2) ---------------------
__global__ void __launch_bounds__(256) k_gemm2(const float* __restrict__ W2l,
                                               const float* __restrict__ W2r,
                                               const float* __restrict__ b2) {
    __shared__ float Asd[16][258];
    __shared__ float Bs[16][80];
    int bm = blockIdx.x * 128;
    int tid = threadIdx.x;
    int tr = tid >> 3;
    int tc = tid & 7;

    float2 acc[4][5];
#pragma unroll
    for (int i = 0; i < 4; i++)
#pragma unroll
        for (int j = 0; j < 5; j++) acc[i][j] = make_float2(0.f, 0.f);

    int arow = tid >> 1;
    int aq   = (tid & 1) * 8;
    int grow = bm + arow;
    bool rowok = grow < NN;

    for (int k0 = 0; k0 < 256; k0 += 16) {
        float4 a0, a1;
        if (rowok) {
            const float* sbase = g_h + (size_t)grow * 256 + k0 + aq;
            a0 = *(const float4*)sbase;
            a1 = *(const float4*)(sbase + 4);
        } else {
            a0 = make_float4(0.f, 0.f, 0.f, 0.f);
            a1 = a0;
        }
        float av[8] = {a0.x, a0.y, a0.z, a0.w, a1.x, a1.y, a1.z, a1.w};
#pragma unroll
        for (int q = 0; q < 8; q++)
            *(float2*)&Asd[aq + q][2 * arow] = make_float2(av[q], av[q]);

#pragma unroll
        for (int i = 0; i < 5; i++) {
            int id = tid + i * 256;
            int kk = id / 80;
            int n  = id % 80;
            Bs[kk][n] = (n < 40) ? W2l[(size_t)(k0 + kk) * 40 + n]
                                 : W2r[(size_t)(k0 + kk) * 40 + (n - 40)];
        }
        __syncthreads();

#pragma unroll
        for (int kk = 0; kk < 16; kk++) {
            float2 a2[4], b2v[5];
#pragma unroll
            for (int i = 0; i < 4; i++) a2[i] = *(float2*)&Asd[kk][2 * (tr + 32 * i)];
#pragma unroll
            for (int j = 0; j < 5; j++) b2v[j] = *(float2*)&Bs[kk][2 * tc + 16 * j];
#pragma unroll
            for (int i = 0; i < 4; i++)
#pragma unroll
                for (int j = 0; j < 5; j++) ffma2(acc[i][j], a2[i], b2v[j]);
        }
        __syncthreads();
    }

#pragma unroll
    for (int i = 0; i < 4; i++) {
        int row = bm + tr + 32 * i;
        if (row < NN) {
#pragma unroll
            for (int j = 0; j < 5; j++) {
                int col = 2 * tc + 16 * j;
                float2 v = acc[i][j];
                if (col < 40) {
                    *(float2*)&g_p[(size_t)row * 40 + col] = v;
                } else {
                    v.x += b2[col - 40];
                    v.y += b2[col - 39];
                    *(float2*)&g_r[(size_t)row * 40 + (col - 40)] = v;
                }
            }
        }
    }
}

// ---------------- layer-2 aggregation + log_softmax --------------------------
__global__ void k_agg2_lsm(float* __restrict__ out) {
    int warp = (blockIdx.x * blockDim.x + threadIdx.x) >> 5;
    if (warp >= NN) return;
    int lane = threadIdx.x & 31;
    int beg = g_offsets[warp], end = g_offsets[warp + 1];
    bool h1 = lane < 8;
    float a0 = 0.f, a1 = 0.f;
    for (int e = beg; e < end; e++) {
        int s = g_esrc[e];
        const float* ps = g_p + (size_t)s * 40;
        a0 += ps[lane];
        if (h1) a1 += ps[32 + lane];
    }
    float iv = g_invc[warp];
    float v0 = a0 * iv + g_r[(size_t)warp * 40 + lane];
    float v1 = h1 ? (a1 * iv + g_r[(size_t)warp * 40 + 32 + lane]) : -3.0e38f;

    float m = fmaxf(v0, v1);
#pragma unroll
    for (int off = 16; off; off >>= 1)
        m = fmaxf(m, __shfl_xor_sync(0xffffffffu, m, off));
    float ssum = expf(v0 - m) + (h1 ? expf(v1 - m) : 0.f);
#pragma unroll
    for (int off = 16; off; off >>= 1)
        ssum += __shfl_xor_sync(0xffffffffu, ssum, off);
    float lse = m + logf(ssum);

    out[(size_t)warp * 40 + lane] = v0 - lse;
    if (h1) out[(size_t)warp * 40 + 32 + lane] = v1 - lse;
}

// ---------------- launch -----------------------------------------------------
extern "C" void kernel_launch(void* const* d_in, const int* in_sizes, int n_in,
                              void* d_out, int out_size) {
    const float* x   = (const float*)d_in[0];
    const void*  ei  = d_in[1];
    const float* W1l = (const float*)d_in[2];
    const float* W1r = (const float*)d_in[3];
    const float* b1  = (const float*)d_in[4];
    const float* W2l = (const float*)d_in[5];
    const float* W2r = (const float*)d_in[6];
    const float* b2  = (const float*)d_in[7];
    float* out = (float*)d_out;

    cudaFuncSetAttribute(k_gemm1_mma, cudaFuncAttributeMaxDynamicSharedMemorySize,
                         DYN_SMEM1);

    k_detect<<<1, 1024>>>((const int*)ei);
    k_zero_counts<<<(NN + 255) / 256, 256>>>();
    k_count<<<(NE + 255) / 256, 256>>>(ei);
    k_scanA<<<NB, 256>>>();
    k_scanB<<<1, 256>>>();
    k_scanC<<<NB, 256>>>();
    k_scatter<<<(NE + 255) / 256, 256>>>(ei);
    k_w1prep<<<256, 256>>>(W1l, W1r);
    k_xconv<<<(NN * 32 + 255) / 256, 256>>>(x);
    k_agg1<<<(NN + 7) / 8, 256>>>(x);
    dim3 g1((NN + 127) / 128, 2);
    k_gemm1_mma<<<g1, 256, DYN_SMEM1>>>(b1);
    k_gemm2<<<(NN + 127) / 128, 256>>>(W2l, W2r, b2);
    k_agg2_lsm<<<(NN + 7) / 8, 256>>>(out);
}

// round 6
// speedup vs baseline: 2.1239x; 1.1595x over previous
#include <cuda_runtime.h>
#include <cuda_bf16.h>
#include <math.h>
#include <cstdint>

#define NN   50000
#define NE   800000
#define IND  128
#define HID  256
#define OUTD 40
#define NB   ((NN + 255) / 256)   // 196 scan blocks

// ---------------- scratch ----------------------------------------------------
__device__ int   g_is64;
__device__ int   g_counts[NN];
__device__ int   g_offsets[NN + 1];
__device__ int   g_cursor[NN];
__device__ int   g_esrc[NE];
__device__ float g_invc[NN];
__device__ int   g_bsum[NB];
__device__ int   g_boff[NB];
__device__ __align__(16) __nv_bfloat16 g_a_hi[(size_t)NN * HID];  // [agg|x] hi
__device__ __align__(16) __nv_bfloat16 g_a_lo[(size_t)NN * HID];  // [agg|x] lo
__device__ __align__(16) __nv_bfloat16 g_w1hi[(size_t)HID * HID]; // W1^T hi [n][k]
__device__ __align__(16) __nv_bfloat16 g_w1lo[(size_t)HID * HID]; // W1^T lo [n][k]
__device__ __align__(16) __nv_bfloat16 g_hhi[(size_t)NN * HID];   // h hi [NN][256]
__device__ __align__(16) __nv_bfloat16 g_hlo[(size_t)NN * HID];   // h lo
__device__ __align__(16) __nv_bfloat16 g_w2hi[(size_t)80 * HID];  // W2^T hi [80][256]
__device__ __align__(16) __nv_bfloat16 g_w2lo[(size_t)80 * HID];  // W2^T lo
__device__ __align__(16) float g_p[(size_t)NN * OUTD];
__device__ __align__(16) float g_r[(size_t)NN * OUTD];

// ---------------- helpers ----------------------------------------------------
__device__ __forceinline__ uint32_t smem_u32(const void* p) {
    uint32_t a;
    asm("{ .reg .u64 t; cvta.to.shared.u64 t, %1; cvt.u32.u64 %0, t; }"
        : "=r"(a) : "l"(p));
    return a;
}

#define SW128(o) ((o) ^ (((o) >> 3) & 0x70))

#define LDSM4(R, ADDR)                                                           \
    asm volatile("ldmatrix.sync.aligned.m8n8.x4.shared.b16 {%0,%1,%2,%3}, [%4];" \
        : "=r"((R)[0]), "=r"((R)[1]), "=r"((R)[2]), "=r"((R)[3]) : "r"(ADDR))

__device__ __forceinline__ void mma16816(float* c, const uint32_t* a,
                                         uint32_t b0, uint32_t b1) {
    asm volatile(
        "mma.sync.aligned.m16n8k16.row.col.f32.bf16.bf16.f32 "
        "{%0,%1,%2,%3}, {%4,%5,%6,%7}, {%8,%9}, {%0,%1,%2,%3};"
        : "+f"(c[0]), "+f"(c[1]), "+f"(c[2]), "+f"(c[3])
        : "r"(a[0]), "r"(a[1]), "r"(a[2]), "r"(a[3]), "r"(b0), "r"(b1));
}

// ---------------- edge dtype detection --------------------------------------
__global__ void k_detect(const int* __restrict__ ei32) {
    __shared__ int bad;
    if (threadIdx.x == 0) bad = 0;
    __syncthreads();
    if (ei32[2 * threadIdx.x + 1] != 0) atomicOr(&bad, 1);
    __syncthreads();
    if (threadIdx.x == 0) g_is64 = bad ? 0 : 1;
}

__device__ __forceinline__ int edge_at(const void* ei, int idx) {
    if (g_is64) return (int)((const long long*)ei)[idx];
    return ((const int*)ei)[idx];
}

// ---------------- CSR build --------------------------------------------------
__global__ void k_zero_counts() {
    int i = blockIdx.x * blockDim.x + threadIdx.x;
    if (i < NN) g_counts[i] = 0;
}

__global__ void k_count(const void* __restrict__ ei) {
    int e = blockIdx.x * blockDim.x + threadIdx.x;
    if (e < NE) atomicAdd(&g_counts[edge_at(ei, NE + e)], 1);
}

__device__ __forceinline__ int block_excl_scan(int c, int t) {
    int lane = t & 31, w = t >> 5;
    int v = c;
#pragma unroll
    for (int off = 1; off < 32; off <<= 1) {
        int n = __shfl_up_sync(0xffffffffu, v, off);
        if (lane >= off) v += n;
    }
    __shared__ int ws[8];
    if (lane == 31) ws[w] = v;
    __syncthreads();
    if (w == 0 && lane < 8) {
        int s = ws[lane];
#pragma unroll
        for (int off = 1; off < 8; off <<= 1) {
            int n = __shfl_up_sync(0x000000ffu, s, off);
            if (lane >= off) s += n;
        }
        ws[lane] = s;
    }
    __syncthreads();
    return v - c + (w > 0 ? ws[w - 1] : 0);
}

__global__ void k_scanA() {
    int i = blockIdx.x * 256 + threadIdx.x;
    int c = (i < NN) ? g_counts[i] : 0;
    int lane = threadIdx.x & 31, w = threadIdx.x >> 5;
#pragma unroll
    for (int off = 16; off; off >>= 1) c += __shfl_xor_sync(0xffffffffu, c, off);
    __shared__ int ws[8];
    if (lane == 0) ws[w] = c;
    __syncthreads();
    if (threadIdx.x == 0) {
        int s = 0;
#pragma unroll
        for (int k = 0; k < 8; k++) s += ws[k];
        g_bsum[blockIdx.x] = s;
    }
}

__global__ void k_scanB() {
    int t = threadIdx.x;
    int v = (t < NB) ? g_bsum[t] : 0;
    int e = block_excl_scan(v, t);
    if (t < NB) g_boff[t] = e;
    if (t == 0) g_offsets[NN] = NE;
}

__global__ void k_scanC() {
    int i = blockIdx.x * 256 + threadIdx.x;
    int c = (i < NN) ? g_counts[i] : 0;
    int e = block_excl_scan(c, threadIdx.x);
    if (i < NN) {
        int off = g_boff[blockIdx.x] + e;
        g_offsets[i] = off;
        g_cursor[i]  = off;
        g_invc[i]    = 1.0f / (float)(c > 1 ? c : 1);
    }
}

__global__ void k_scatter(const void* __restrict__ ei) {
    int e = blockIdx.x * blockDim.x + threadIdx.x;
    if (e < NE) {
        int s = edge_at(ei, e);
        int d = edge_at(ei, NE + e);
        g_esrc[atomicAdd(&g_cursor[d], 1)] = s;
    }
}

// ---------------- bf16 split helpers -----------------------------------------
__device__ __forceinline__ void split4(float4 v, uint2& hi, uint2& lo) {
    __nv_bfloat16 h0 = __float2bfloat16(v.x);
    __nv_bfloat16 h1 = __float2bfloat16(v.y);
    __nv_bfloat16 h2 = __float2bfloat16(v.z);
    __nv_bfloat16 h3 = __float2bfloat16(v.w);
    __nv_bfloat16 l0 = __float2bfloat16(v.x - __bfloat162float(h0));
    __nv_bfloat16 l1 = __float2bfloat16(v.y - __bfloat162float(h1));
    __nv_bfloat16 l2 = __float2bfloat16(v.z - __bfloat162float(h2));
    __nv_bfloat16 l3 = __float2bfloat16(v.w - __bfloat162float(h3));
    hi.x = (uint32_t)__bfloat16_as_ushort(h0) | ((uint32_t)__bfloat16_as_ushort(h1) << 16);
    hi.y = (uint32_t)__bfloat16_as_ushort(h2) | ((uint32_t)__bfloat16_as_ushort(h3) << 16);
    lo.x = (uint32_t)__bfloat16_as_ushort(l0) | ((uint32_t)__bfloat16_as_ushort(l1) << 16);
    lo.y = (uint32_t)__bfloat16_as_ushort(l2) | ((uint32_t)__bfloat16_as_ushort(l3) << 16);
}

__device__ __forceinline__ void split2(float x, float y, uint32_t& hi, uint32_t& lo) {
    __nv_bfloat16 hx = __float2bfloat16(x), hy = __float2bfloat16(y);
    __nv_bfloat16 lx = __float2bfloat16(x - __bfloat162float(hx));
    __nv_bfloat16 ly = __float2bfloat16(y - __bfloat162float(hy));
    hi = (uint32_t)__bfloat16_as_ushort(hx) | ((uint32_t)__bfloat16_as_ushort(hy) << 16);
    lo = (uint32_t)__bfloat16_as_ushort(lx) | ((uint32_t)__bfloat16_as_ushort(ly) << 16);
}

// ---------------- W1 prep: transpose + bf16-split into [n][k] ----------------
__global__ void k_w1prep(const float* __restrict__ W1l,
                         const float* __restrict__ W1r) {
    int idx = blockIdx.x * 256 + threadIdx.x;   // 65536
    int n = idx >> 8, k = idx & 255;
    float w = (k < 128) ? W1l[(size_t)k * 256 + n]
                        : W1r[(size_t)(k - 128) * 256 + n];
    __nv_bfloat16 h = __float2bfloat16(w);
    __nv_bfloat16 l = __float2bfloat16(w - __bfloat162float(h));
    g_w1hi[(size_t)n * 256 + k] = h;
    g_w1lo[(size_t)n * 256 + k] = l;
}

// ---------------- W2 prep: [n=80][k=256] hi/lo, n<40 -> W2l, else W2r --------
__global__ void k_w2prep(const float* __restrict__ W2l,
                         const float* __restrict__ W2r) {
    int idx = blockIdx.x * 256 + threadIdx.x;   // 20480
    if (idx >= 80 * 256) return;
    int n = idx >> 8, k = idx & 255;
    float w = (n < 40) ? W2l[(size_t)k * 40 + n]
                       : W2r[(size_t)k * 40 + (n - 40)];
    __nv_bfloat16 h = __float2bfloat16(w);
    __nv_bfloat16 l = __float2bfloat16(w - __bfloat162float(h));
    g_w2hi[(size_t)n * 256 + k] = h;
    g_w2lo[(size_t)n * 256 + k] = l;
}

// ---------------- x conversion into cols 128..255 of A -----------------------
__global__ void k_xconv(const float* __restrict__ x) {
    int idx = blockIdx.x * 256 + threadIdx.x;
    if (idx >= NN * 32) return;
    int row = idx >> 5, c4 = idx & 31;
    float4 v = ((const float4*)x)[(size_t)row * 32 + c4];
    uint2 hi, lo;
    split4(v, hi, lo);
    *(uint2*)&g_a_hi[(size_t)row * 256 + 128 + c4 * 4] = hi;
    *(uint2*)&g_a_lo[(size_t)row * 256 + 128 + c4 * 4] = lo;
}

// ---------------- layer-1 aggregation (bf16 hi/lo cols 0..127) ---------------
__global__ void k_agg1(const float* __restrict__ x) {
    int warp = (blockIdx.x * blockDim.x + threadIdx.x) >> 5;
    if (warp >= NN) return;
    int lane = threadIdx.x & 31;
    int beg = g_offsets[warp], end = g_offsets[warp + 1];
    const float4* __restrict__ x4 = (const float4*)x;
    float4 acc = make_float4(0.f, 0.f, 0.f, 0.f);
    int e = beg;
    for (; e + 1 < end; e += 2) {
        int s0 = g_esrc[e];
        int s1 = g_esrc[e + 1];
        float4 v0 = x4[(size_t)s0 * 32 + lane];
        float4 v1 = x4[(size_t)s1 * 32 + lane];
        acc.x += v0.x + v1.x; acc.y += v0.y + v1.y;
        acc.z += v0.z + v1.z; acc.w += v0.w + v1.w;
    }
    if (e < end) {
        int s0 = g_esrc[e];
        float4 v0 = x4[(size_t)s0 * 32 + lane];
        acc.x += v0.x; acc.y += v0.y; acc.z += v0.z; acc.w += v0.w;
    }
    float iv = g_invc[warp];
    float4 o = make_float4(acc.x * iv, acc.y * iv, acc.z * iv, acc.w * iv);
    uint2 hi, lo;
    split4(o, hi, lo);
    *(uint2*)&g_a_hi[(size_t)warp * 256 + lane * 4] = hi;
    *(uint2*)&g_a_lo[(size_t)warp * 256 + lane * 4] = lo;
}

// ---------------- GEMM1 via mma.sync (bf16 3-pass split) ---------------------
// h = relu(A @ W1^T + b1).  Writes h as bf16 hi/lo.
// Block tile 128x128, grid (391, 2); 8 warps, warp tile 32x64.
#define GA_H 0
#define GA_L 16384
#define GB_H 32768
#define GB_L 49152
#define DYN_SMEM1 65536

__global__ void __launch_bounds__(256, 1) k_gemm1_mma(const float* __restrict__ b1) {
    extern __shared__ char dsm[];
    int tid = threadIdx.x;
    int wid = tid >> 5;
    int lane = tid & 31;
    int bm = blockIdx.x * 128;
    int bn = blockIdx.y * 128;
    uint32_t dynb = smem_u32(dsm);

    int warp_m = (wid & 3) * 32;
    int warp_n = (wid >> 2) * 64;

    uint32_t offA[2][4], offB[4][4];
    {
        int mat = lane >> 3, rr = lane & 7;
#pragma unroll
        for (int i = 0; i < 2; i++)
#pragma unroll
            for (int j = 0; j < 4; j++) {
                int row = warp_m + i * 16 + ((mat & 1) << 3) + rr;
                int kb  = j * 16 + ((mat >> 1) << 3);
                offA[i][j] = SW128(row * 128 + kb * 2);
            }
#pragma unroll
        for (int q = 0; q < 4; q++)
#pragma unroll
            for (int j = 0; j < 4; j++) {
                int n  = warp_n + q * 16 + ((mat & 2) << 2) + rr;
                int kb = j * 16 + ((mat & 1) << 3);
                offB[q][j] = SW128(n * 128 + kb * 2);
            }
    }

    float acc[2][8][4];
#pragma unroll
    for (int i = 0; i < 2; i++)
#pragma unroll
        for (int jn = 0; jn < 8; jn++)
#pragma unroll
            for (int t = 0; t < 4; t++) acc[i][jn][t] = 0.f;

    for (int k0 = 0; k0 < 256; k0 += 64) {
#pragma unroll
        for (int it = 0; it < 4; it++) {
            int idx = tid + it * 256;
            int row = idx >> 3, seg = idx & 7;
            int grow = bm + row;
            int4 vh = make_int4(0, 0, 0, 0), vl = make_int4(0, 0, 0, 0);
            if (grow < NN) {
                size_t boff = ((size_t)grow * 256 + k0 + seg * 8) * 2;
                vh = *(const int4*)((const char*)g_a_hi + boff);
                vl = *(const int4*)((const char*)g_a_lo + boff);
            }
            int so = SW128(row * 128 + seg * 16);
            *(int4*)(dsm + GA_H + so) = vh;
            *(int4*)(dsm + GA_L + so) = vl;
        }
#pragma unroll
        for (int it = 0; it < 4; it++) {
            int idx = tid + it * 256;
            int row = idx >> 3, seg = idx & 7;
            size_t boff = ((size_t)(bn + row) * 256 + k0 + seg * 8) * 2;
            int4 vh = *(const int4*)((const char*)g_w1hi + boff);
            int4 vl = *(const int4*)((const char*)g_w1lo + boff);
            int so = SW128(row * 128 + seg * 16);
            *(int4*)(dsm + GB_H + so) = vh;
            *(int4*)(dsm + GB_L + so) = vl;
        }
        __syncthreads();

#pragma unroll
        for (int j = 0; j < 4; j++) {
            uint32_t ah[2][4], al[2][4], bh[4][4], bl[4][4];
#pragma unroll
            for (int i = 0; i < 2; i++) {
                LDSM4(ah[i], dynb + GA_H + offA[i][j]);
                LDSM4(al[i], dynb + GA_L + offA[i][j]);
            }
#pragma unroll
            for (int q = 0; q < 4; q++) {
                LDSM4(bh[q], dynb + GB_H + offB[q][j]);
                LDSM4(bl[q], dynb + GB_L + offB[q][j]);
            }
#pragma unroll
            for (int i = 0; i < 2; i++)
#pragma unroll
                for (int jn = 0; jn < 8; jn++) {
                    int q = jn >> 1, hsel = (jn & 1) * 2;
                    uint32_t bh0 = bh[q][hsel], bh1 = bh[q][hsel + 1];
                    uint32_t bl0 = bl[q][hsel], bl1 = bl[q][hsel + 1];
                    mma16816(acc[i][jn], ah[i], bh0, bh1);
                    mma16816(acc[i][jn], ah[i], bl0, bl1);
                    mma16816(acc[i][jn], al[i], bh0, bh1);
                }
        }
        __syncthreads();
    }

    // epilogue: bias + relu, then bf16 hi/lo split stores
    int r0 = bm + warp_m + (lane >> 2);
    int c0 = bn + warp_n + 2 * (lane & 3);
#pragma unroll
    for (int i = 0; i < 2; i++) {
        int row = r0 + i * 16;
#pragma unroll
        for (int jn = 0; jn < 8; jn++) {
            int col = c0 + jn * 8;
            float bx = b1[col], by = b1[col + 1];
            if (row < NN) {
                float vx = acc[i][jn][0] + bx; vx = vx > 0.f ? vx : 0.f;
                float vy = acc[i][jn][1] + by; vy = vy > 0.f ? vy : 0.f;
                uint32_t hi, lo;
                split2(vx, vy, hi, lo);
                *(uint32_t*)&g_hhi[(size_t)row * 256 + col] = hi;
                *(uint32_t*)&g_hlo[(size_t)row * 256 + col] = lo;
            }
            if (row + 8 < NN) {
                float vx = acc[i][jn][2] + bx; vx = vx > 0.f ? vx : 0.f;
                float vy = acc[i][jn][3] + by; vy = vy > 0.f ? vy : 0.f;
                uint32_t hi, lo;
                split2(vx, vy, hi, lo);
                *(uint32_t*)&g_hhi[(size_t)(row + 8) * 256 + col] = hi;
                *(uint32_t*)&g_hlo[(size_t)(row + 8) * 256 + col] = lo;
            }
        }
    }
}

// ---------------- GEMM2 via mma.sync: [p|r] = h @ W2^T -----------------------
// Block tile 128x80 (full N), 8 warps, warp tile 16x80; K chunks of 64.
#define G2A_H 0
#define G2A_L 16384
#define G2B_H 32768
#define G2B_L 43008
#define DYN_SMEM2 53248

__global__ void __launch_bounds__(256, 1) k_gemm2_mma(const float* __restrict__ b2) {
    extern __shared__ char dsm[];
    int tid = threadIdx.x;
    int wid = tid >> 5;
    int lane = tid & 31;
    int bm = blockIdx.x * 128;
    uint32_t dynb = smem_u32(dsm);

    int warp_m = wid * 16;

    uint32_t offA[4], offB[5][4];
    {
        int mat = lane >> 3, rr = lane & 7;
#pragma unroll
        for (int j = 0; j < 4; j++) {
            int row = warp_m + ((mat & 1) << 3) + rr;
            int kb  = j * 16 + ((mat >> 1) << 3);
            offA[j] = SW128(row * 128 + kb * 2);
        }
#pragma unroll
        for (int q = 0; q < 5; q++)
#pragma unroll
            for (int j = 0; j < 4; j++) {
                int n  = q * 16 + ((mat & 2) << 2) + rr;
                int kb = j * 16 + ((mat & 1) << 3);
                offB[q][j] = SW128(n * 128 + kb * 2);
            }
    }

    float acc[10][4];
#pragma unroll
    for (int jn = 0; jn < 10; jn++)
#pragma unroll
        for (int t = 0; t < 4; t++) acc[jn][t] = 0.f;

    for (int k0 = 0; k0 < 256; k0 += 64) {
        // stage A (h) hi/lo: 128 rows x 64 k
#pragma unroll
        for (int it = 0; it < 4; it++) {
            int idx = tid + it * 256;
            int row = idx >> 3, seg = idx & 7;
            int grow = bm + row;
            int4 vh = make_int4(0, 0, 0, 0), vl = make_int4(0, 0, 0, 0);
            if (grow < NN) {
                size_t boff = ((size_t)grow * 256 + k0 + seg * 8) * 2;
                vh = *(const int4*)((const char*)g_hhi + boff);
                vl = *(const int4*)((const char*)g_hlo + boff);
            }
            int so = SW128(row * 128 + seg * 16);
            *(int4*)(dsm + G2A_H + so) = vh;
            *(int4*)(dsm + G2A_L + so) = vl;
        }
        // stage B hi/lo: 80 rows x 64 k (640 int4 each)
#pragma unroll
        for (int it = 0; it < 3; it++) {
            int idx = tid + it * 256;
            if (idx < 640) {
                int row = idx >> 3, seg = idx & 7;
                size_t boff = ((size_t)row * 256 + k0 + seg * 8) * 2;
                int4 vh = *(const int4*)((const char*)g_w2hi + boff);
                int4 vl = *(const int4*)((const char*)g_w2lo + boff);
                int so = SW128(row * 128 + seg * 16);
                *(int4*)(dsm + G2B_H + so) = vh;
                *(int4*)(dsm + G2B_L + so) = vl;
            }
        }
        __syncthreads();

#pragma unroll
        for (int j = 0; j < 4; j++) {
            uint32_t ah[4], al[4], bh[5][4], bl[5][4];
            LDSM4(ah, dynb + G2A_H + offA[j]);
            LDSM4(al, dynb + G2A_L + offA[j]);
#pragma unroll
            for (int q = 0; q < 5; q++) {
                LDSM4(bh[q], dynb + G2B_H + offB[q][j]);
                LDSM4(bl[q], dynb + G2B_L + offB[q][j]);
            }
#pragma unroll
            for (int jn = 0; jn < 10; jn++) {
                int q = jn >> 1, hsel = (jn & 1) * 2;
                uint32_t bh0 = bh[q][hsel], bh1 = bh[q][hsel + 1];
                uint32_t bl0 = bl[q][hsel], bl1 = bl[q][hsel + 1];
                mma16816(acc[jn], ah, bh0, bh1);
                mma16816(acc[jn], ah, bl0, bl1);
                mma16816(acc[jn], al, bh0, bh1);
            }
        }
        __syncthreads();
    }

    // epilogue: cols<40 -> p (no bias), cols>=40 -> r (+b2)
    int r0 = bm + warp_m + (lane >> 2);
    int c0 = 2 * (lane & 3);
#pragma unroll
    for (int jn = 0; jn < 10; jn++) {
        int col = c0 + jn * 8;
#pragma unroll
        for (int half = 0; half < 2; half++) {
            int row = r0 + half * 8;
            if (row < NN) {
                float vx = acc[jn][half * 2 + 0];
                float vy = acc[jn][half * 2 + 1];
                if (col < 40) {
                    float2 v = make_float2(vx, vy);
                    *(float2*)&g_p[(size_t)row * 40 + col] = v;
                } else {
                    float2 v = make_float2(vx + b2[col - 40], vy + b2[col - 39]);
                    *(float2*)&g_r[(size_t)row * 40 + (col - 40)] = v;
                }
            }
        }
    }
}

// ---------------- layer-2 aggregation + log_softmax --------------------------
__global__ void k_agg2_lsm(float* __restrict__ out) {
    int warp = (blockIdx.x * blockDim.x + threadIdx.x) >> 5;
    if (warp >= NN) return;
    int lane = threadIdx.x & 31;
    int beg = g_offsets[warp], end = g_offsets[warp + 1];
    bool h1 = lane < 8;
    float a0 = 0.f, a1 = 0.f;
    for (int e = beg; e < end; e++) {
        int s = g_esrc[e];
        const float* ps = g_p + (size_t)s * 40;
        a0 += ps[lane];
        if (h1) a1 += ps[32 + lane];
    }
    float iv = g_invc[warp];
    float v0 = a0 * iv + g_r[(size_t)warp * 40 + lane];
    float v1 = h1 ? (a1 * iv + g_r[(size_t)warp * 40 + 32 + lane]) : -3.0e38f;

    float m = fmaxf(v0, v1);
#pragma unroll
    for (int off = 16; off; off >>= 1)
        m = fmaxf(m, __shfl_xor_sync(0xffffffffu, m, off));
    float ssum = expf(v0 - m) + (h1 ? expf(v1 - m) : 0.f);
#pragma unroll
    for (int off = 16; off; off >>= 1)
        ssum += __shfl_xor_sync(0xffffffffu, ssum, off);
    float lse = m + logf(ssum);

    out[(size_t)warp * 40 + lane] = v0 - lse;
    if (h1) out[(size_t)warp * 40 + 32 + lane] = v1 - lse;
}

// ---------------- launch -----------------------------------------------------
extern "C" void kernel_launch(void* const* d_in, const int* in_sizes, int n_in,
                              void* d_out, int out_size) {
    const float* x   = (const float*)d_in[0];
    const void*  ei  = d_in[1];
    const float* W1l = (const float*)d_in[2];
    const float* W1r = (const float*)d_in[3];
    const float* b1  = (const float*)d_in[4];
    const float* W2l = (const float*)d_in[5];
    const float* W2r = (const float*)d_in[6];
    const float* b2  = (const float*)d_in[7];
    float* out = (float*)d_out;

    cudaFuncSetAttribute(k_gemm1_mma, cudaFuncAttributeMaxDynamicSharedMemorySize,
                         DYN_SMEM1);
    cudaFuncSetAttribute(k_gemm2_mma, cudaFuncAttributeMaxDynamicSharedMemorySize,
                         DYN_SMEM2);

    k_detect<<<1, 1024>>>((const int*)ei);
    k_zero_counts<<<(NN + 255) / 256, 256>>>();
    k_count<<<(NE + 255) / 256, 256>>>(ei);
    k_scanA<<<NB, 256>>>();
    k_scanB<<<1, 256>>>();
    k_scanC<<<NB, 256>>>();
    k_scatter<<<(NE + 255) / 256, 256>>>(ei);
    k_w1prep<<<256, 256>>>(W1l, W1r);
    k_w2prep<<<80, 256>>>(W2l, W2r);
    k_xconv<<<(NN * 32 + 255) / 256, 256>>>(x);
    k_agg1<<<(NN + 7) / 8, 256>>>(x);
    dim3 g1((NN + 127) / 128, 2);
    k_gemm1_mma<<<g1, 256, DYN_SMEM1>>>(b1);
    k_gemm2_mma<<<(NN + 127) / 128, 256, DYN_SMEM2>>>(b2);
    k_agg2_lsm<<<(NN + 7) / 8, 256>>>(out);
}

// round 7
// speedup vs baseline: 2.3900x; 1.1253x over previous
#include <cuda_runtime.h>
#include <cuda_bf16.h>
#include <math.h>
#include <cstdint>

#define NN   50000
#define NE   800000
#define IND  128
#define HID  256
#define OUTD 40
#define NB   ((NN + 255) / 256)   // 196 scan blocks

// ---------------- scratch ----------------------------------------------------
__device__ int   g_is64;
__device__ int   g_counts[NN];
__device__ int   g_offsets[NN + 1];
__device__ int   g_cursor[NN];
__device__ int   g_esrc[NE];
__device__ float g_invc[NN];
__device__ int   g_bsum[NB];
__device__ int   g_boff[NB];
__device__ __align__(16) __nv_bfloat16 g_a_hi[(size_t)NN * HID];  // [agg|x] hi
__device__ __align__(16) __nv_bfloat16 g_a_lo[(size_t)NN * HID];  // [agg|x] lo
__device__ __align__(16) __nv_bfloat16 g_w1hi[(size_t)HID * HID]; // W1^T hi [n][k]
__device__ __align__(16) __nv_bfloat16 g_w1lo[(size_t)HID * HID]; // W1^T lo [n][k]
__device__ __align__(16) __nv_bfloat16 g_hhi[(size_t)NN * HID];   // h hi [NN][256]
__device__ __align__(16) __nv_bfloat16 g_hlo[(size_t)NN * HID];   // h lo
__device__ __align__(16) __nv_bfloat16 g_w2hi[(size_t)80 * HID];  // W2^T hi [80][256]
__device__ __align__(16) __nv_bfloat16 g_w2lo[(size_t)80 * HID];  // W2^T lo
__device__ __align__(16) float g_p[(size_t)NN * OUTD];
__device__ __align__(16) float g_r[(size_t)NN * OUTD];

// ---------------- helpers ----------------------------------------------------
__device__ __forceinline__ uint32_t smem_u32(const void* p) {
    uint32_t a;
    asm("{ .reg .u64 t; cvta.to.shared.u64 t, %1; cvt.u32.u64 %0, t; }"
        : "=r"(a) : "l"(p));
    return a;
}

#define SW128(o) ((o) ^ (((o) >> 3) & 0x70))

#define LDSM4(R, ADDR)                                                           \
    asm volatile("ldmatrix.sync.aligned.m8n8.x4.shared.b16 {%0,%1,%2,%3}, [%4];" \
        : "=r"((R)[0]), "=r"((R)[1]), "=r"((R)[2]), "=r"((R)[3]) : "r"(ADDR))

__device__ __forceinline__ void mma16816(float* c, const uint32_t* a,
                                         uint32_t b0, uint32_t b1) {
    asm volatile(
        "mma.sync.aligned.m16n8k16.row.col.f32.bf16.bf16.f32 "
        "{%0,%1,%2,%3}, {%4,%5,%6,%7}, {%8,%9}, {%0,%1,%2,%3};"
        : "+f"(c[0]), "+f"(c[1]), "+f"(c[2]), "+f"(c[3])
        : "r"(a[0]), "r"(a[1]), "r"(a[2]), "r"(a[3]), "r"(b0), "r"(b1));
}

__device__ __forceinline__ void cp_async16(uint32_t dst, const void* src, int srcsz) {
    asm volatile("cp.async.cg.shared.global [%0], [%1], 16, %2;"
                 :: "r"(dst), "l"(src), "r"(srcsz) : "memory");
}
#define CP_COMMIT() asm volatile("cp.async.commit_group;" ::: "memory")
#define CP_WAIT1()  asm volatile("cp.async.wait_group 1;" ::: "memory")

// ---------------- edge dtype detection --------------------------------------
__global__ void k_detect(const int* __restrict__ ei32) {
    __shared__ int bad;
    if (threadIdx.x == 0) bad = 0;
    __syncthreads();
    if (ei32[2 * threadIdx.x + 1] != 0) atomicOr(&bad, 1);
    __syncthreads();
    if (threadIdx.x == 0) g_is64 = bad ? 0 : 1;
}

__device__ __forceinline__ int edge_at(const void* ei, int idx) {
    if (g_is64) return (int)((const long long*)ei)[idx];
    return ((const int*)ei)[idx];
}

// ---------------- CSR build --------------------------------------------------
__global__ void k_zero_counts() {
    int i = blockIdx.x * blockDim.x + threadIdx.x;
    if (i < NN) g_counts[i] = 0;
}

__global__ void k_count(const void* __restrict__ ei) {
    int e = blockIdx.x * blockDim.x + threadIdx.x;
    if (e < NE) atomicAdd(&g_counts[edge_at(ei, NE + e)], 1);
}

__device__ __forceinline__ int block_excl_scan(int c, int t) {
    int lane = t & 31, w = t >> 5;
    int v = c;
#pragma unroll
    for (int off = 1; off < 32; off <<= 1) {
        int n = __shfl_up_sync(0xffffffffu, v, off);
        if (lane >= off) v += n;
    }
    __shared__ int ws[8];
    if (lane == 31) ws[w] = v;
    __syncthreads();
    if (w == 0 && lane < 8) {
        int s = ws[lane];
#pragma unroll
        for (int off = 1; off < 8; off <<= 1) {
            int n = __shfl_up_sync(0x000000ffu, s, off);
            if (lane >= off) s += n;
        }
        ws[lane] = s;
    }
    __syncthreads();
    return v - c + (w > 0 ? ws[w - 1] : 0);
}

__global__ void k_scanA() {
    int i = blockIdx.x * 256 + threadIdx.x;
    int c = (i < NN) ? g_counts[i] : 0;
    int lane = threadIdx.x & 31, w = threadIdx.x >> 5;
#pragma unroll
    for (int off = 16; off; off >>= 1) c += __shfl_xor_sync(0xffffffffu, c, off);
    __shared__ int ws[8];
    if (lane == 0) ws[w] = c;
    __syncthreads();
    if (threadIdx.x == 0) {
        int s = 0;
#pragma unroll
        for (int k = 0; k < 8; k++) s += ws[k];
        g_bsum[blockIdx.x] = s;
    }
}

__global__ void k_scanB() {
    int t = threadIdx.x;
    int v = (t < NB) ? g_bsum[t] : 0;
    int e = block_excl_scan(v, t);
    if (t < NB) g_boff[t] = e;
    if (t == 0) g_offsets[NN] = NE;
}

__global__ void k_scanC() {
    int i = blockIdx.x * 256 + threadIdx.x;
    int c = (i < NN) ? g_counts[i] : 0;
    int e = block_excl_scan(c, threadIdx.x);
    if (i < NN) {
        int off = g_boff[blockIdx.x] + e;
        g_offsets[i] = off;
        g_cursor[i]  = off;
        g_invc[i]    = 1.0f / (float)(c > 1 ? c : 1);
    }
}

__global__ void k_scatter(const void* __restrict__ ei) {
    int e = blockIdx.x * blockDim.x + threadIdx.x;
    if (e < NE) {
        int s = edge_at(ei, e);
        int d = edge_at(ei, NE + e);
        g_esrc[atomicAdd(&g_cursor[d], 1)] = s;
    }
}

// ---------------- bf16 split helpers -----------------------------------------
__device__ __forceinline__ void split4(float4 v, uint2& hi, uint2& lo) {
    __nv_bfloat16 h0 = __float2bfloat16(v.x);
    __nv_bfloat16 h1 = __float2bfloat16(v.y);
    __nv_bfloat16 h2 = __float2bfloat16(v.z);
    __nv_bfloat16 h3 = __float2bfloat16(v.w);
    __nv_bfloat16 l0 = __float2bfloat16(v.x - __bfloat162float(h0));
    __nv_bfloat16 l1 = __float2bfloat16(v.y - __bfloat162float(h1));
    __nv_bfloat16 l2 = __float2bfloat16(v.z - __bfloat162float(h2));
    __nv_bfloat16 l3 = __float2bfloat16(v.w - __bfloat162float(h3));
    hi.x = (uint32_t)__bfloat16_as_ushort(h0) | ((uint32_t)__bfloat16_as_ushort(h1) << 16);
    hi.y = (uint32_t)__bfloat16_as_ushort(h2) | ((uint32_t)__bfloat16_as_ushort(h3) << 16);
    lo.x = (uint32_t)__bfloat16_as_ushort(l0) | ((uint32_t)__bfloat16_as_ushort(l1) << 16);
    lo.y = (uint32_t)__bfloat16_as_ushort(l2) | ((uint32_t)__bfloat16_as_ushort(l3) << 16);
}

__device__ __forceinline__ void split2(float x, float y, uint32_t& hi, uint32_t& lo) {
    __nv_bfloat16 hx = __float2bfloat16(x), hy = __float2bfloat16(y);
    __nv_bfloat16 lx = __float2bfloat16(x - __bfloat162float(hx));
    __nv_bfloat16 ly = __float2bfloat16(y - __bfloat162float(hy));
    hi = (uint32_t)__bfloat16_as_ushort(hx) | ((uint32_t)__bfloat16_as_ushort(hy) << 16);
    lo = (uint32_t)__bfloat16_as_ushort(lx) | ((uint32_t)__bfloat16_as_ushort(ly) << 16);
}

// ---------------- merged prep: W1, W2, x conversion --------------------------
// blocks [0,256): W1^T split; [256,336): W2^T split; [336,6586): x split
__global__ void k_prep(const float* __restrict__ W1l, const float* __restrict__ W1r,
                       const float* __restrict__ W2l, const float* __restrict__ W2r,
                       const float* __restrict__ x) {
    int b = blockIdx.x;
    int tid = threadIdx.x;
    if (b < 256) {
        int idx = b * 256 + tid;
        int n = idx >> 8, k = idx & 255;
        float w = (k < 128) ? W1l[(size_t)k * 256 + n]
                            : W1r[(size_t)(k - 128) * 256 + n];
        __nv_bfloat16 h = __float2bfloat16(w);
        __nv_bfloat16 l = __float2bfloat16(w - __bfloat162float(h));
        g_w1hi[(size_t)n * 256 + k] = h;
        g_w1lo[(size_t)n * 256 + k] = l;
    } else if (b < 336) {
        int idx = (b - 256) * 256 + tid;
        int n = idx >> 8, k = idx & 255;
        float w = (n < 40) ? W2l[(size_t)k * 40 + n]
                           : W2r[(size_t)k * 40 + (n - 40)];
        __nv_bfloat16 h = __float2bfloat16(w);
        __nv_bfloat16 l = __float2bfloat16(w - __bfloat162float(h));
        g_w2hi[(size_t)n * 256 + k] = h;
        g_w2lo[(size_t)n * 256 + k] = l;
    } else {
        int idx = (b - 336) * 256 + tid;
        if (idx >= NN * 32) return;
        int row = idx >> 5, c4 = idx & 31;
        float4 v = ((const float4*)x)[(size_t)row * 32 + c4];
        uint2 hi, lo;
        split4(v, hi, lo);
        *(uint2*)&g_a_hi[(size_t)row * 256 + 128 + c4 * 4] = hi;
        *(uint2*)&g_a_lo[(size_t)row * 256 + 128 + c4 * 4] = lo;
    }
}

// ---------------- layer-1 aggregation (bf16 hi/lo cols 0..127) ---------------
__global__ void k_agg1(const float* __restrict__ x) {
    int warp = (blockIdx.x * blockDim.x + threadIdx.x) >> 5;
    if (warp >= NN) return;
    int lane = threadIdx.x & 31;
    int beg = g_offsets[warp], end = g_offsets[warp + 1];
    const float4* __restrict__ x4 = (const float4*)x;
    float4 acc = make_float4(0.f, 0.f, 0.f, 0.f);
    int e = beg;
    for (; e + 1 < end; e += 2) {
        int s0 = g_esrc[e];
        int s1 = g_esrc[e + 1];
        float4 v0 = x4[(size_t)s0 * 32 + lane];
        float4 v1 = x4[(size_t)s1 * 32 + lane];
        acc.x += v0.x + v1.x; acc.y += v0.y + v1.y;
        acc.z += v0.z + v1.z; acc.w += v0.w + v1.w;
    }
    if (e < end) {
        int s0 = g_esrc[e];
        float4 v0 = x4[(size_t)s0 * 32 + lane];
        acc.x += v0.x; acc.y += v0.y; acc.z += v0.z; acc.w += v0.w;
    }
    float iv = g_invc[warp];
    float4 o = make_float4(acc.x * iv, acc.y * iv, acc.z * iv, acc.w * iv);
    uint2 hi, lo;
    split4(o, hi, lo);
    *(uint2*)&g_a_hi[(size_t)warp * 256 + lane * 4] = hi;
    *(uint2*)&g_a_lo[(size_t)warp * 256 + lane * 4] = lo;
}

// ---------------- GEMM1 via mma.sync (bf16 3-pass split, cp.async pipe) ------
// h = relu(A @ W1^T + b1).  Block tile 128x128, grid (391, 2); warp tile 32x64.
#define GA_H 0
#define GA_L 16384
#define GB_H 32768
#define GB_L 49152
#define BUF1 65536
#define DYN_SMEM1 (2 * BUF1)

__global__ void __launch_bounds__(256, 1) k_gemm1_mma(const float* __restrict__ b1) {
    extern __shared__ char dsm[];
    int tid = threadIdx.x;
    int wid = tid >> 5;
    int lane = tid & 31;
    int bm = blockIdx.x * 128;
    int bn = blockIdx.y * 128;
    uint32_t dynb = smem_u32(dsm);

    int warp_m = (wid & 3) * 32;
    int warp_n = (wid >> 2) * 64;

    uint32_t offA[2][4], offB[4][4];
    {
        int mat = lane >> 3, rr = lane & 7;
#pragma unroll
        for (int i = 0; i < 2; i++)
#pragma unroll
            for (int j = 0; j < 4; j++) {
                int row = warp_m + i * 16 + ((mat & 1) << 3) + rr;
                int kb  = j * 16 + ((mat >> 1) << 3);
                offA[i][j] = SW128(row * 128 + kb * 2);
            }
#pragma unroll
        for (int q = 0; q < 4; q++)
#pragma unroll
            for (int j = 0; j < 4; j++) {
                int n  = warp_n + q * 16 + ((mat & 2) << 2) + rr;
                int kb = j * 16 + ((mat & 1) << 3);
                offB[q][j] = SW128(n * 128 + kb * 2);
            }
    }

    float acc[2][8][4];
#pragma unroll
    for (int i = 0; i < 2; i++)
#pragma unroll
        for (int jn = 0; jn < 8; jn++)
#pragma unroll
            for (int t = 0; t < 4; t++) acc[i][jn][t] = 0.f;

    // staging indices (fixed per thread)
    int arow = tid >> 1;                 // A: 2 threads/row, 4 iters -> 128 rows
    int brow = tid >> 1;

#define STAGE1(K0, BUFO) do {                                                      \
    _Pragma("unroll")                                                              \
    for (int it = 0; it < 4; it++) {                                               \
        int idx = tid + it * 256;                                                  \
        int row = idx >> 3, seg = idx & 7;                                         \
        int grow = bm + row;                                                       \
        int cl = grow < NN ? grow : (NN - 1);                                      \
        int sz = grow < NN ? 16 : 0;                                               \
        size_t boff = ((size_t)cl * 256 + (K0) + seg * 8) * 2;                     \
        int so = SW128(row * 128 + seg * 16);                                      \
        cp_async16(dynb + (BUFO) + GA_H + so, (const char*)g_a_hi + boff, sz);     \
        cp_async16(dynb + (BUFO) + GA_L + so, (const char*)g_a_lo + boff, sz);     \
    }                                                                              \
    _Pragma("unroll")                                                              \
    for (int it = 0; it < 4; it++) {                                               \
        int idx = tid + it * 256;                                                  \
        int row = idx >> 3, seg = idx & 7;                                         \
        size_t boff = ((size_t)(bn + row) * 256 + (K0) + seg * 8) * 2;             \
        int so = SW128(row * 128 + seg * 16);                                      \
        cp_async16(dynb + (BUFO) + GB_H + so, (const char*)g_w1hi + boff, 16);     \
        cp_async16(dynb + (BUFO) + GB_L + so, (const char*)g_w1lo + boff, 16);     \
    }                                                                              \
} while (0)

    STAGE1(0, 0);     CP_COMMIT();
    STAGE1(64, BUF1); CP_COMMIT();

    for (int kc = 0; kc < 4; kc++) {
        uint32_t bufo = (kc & 1) ? BUF1 : 0;
        CP_WAIT1();
        __syncthreads();
#pragma unroll
        for (int j = 0; j < 4; j++) {
            uint32_t ah[2][4], al[2][4], bh[4][4], bl[4][4];
#pragma unroll
            for (int i = 0; i < 2; i++) {
                LDSM4(ah[i], dynb + bufo + GA_H + offA[i][j]);
                LDSM4(al[i], dynb + bufo + GA_L + offA[i][j]);
            }
#pragma unroll
            for (int q = 0; q < 4; q++) {
                LDSM4(bh[q], dynb + bufo + GB_H + offB[q][j]);
                LDSM4(bl[q], dynb + bufo + GB_L + offB[q][j]);
            }
#pragma unroll
            for (int i = 0; i < 2; i++)
#pragma unroll
                for (int jn = 0; jn < 8; jn++) {
                    int q = jn >> 1, hsel = (jn & 1) * 2;
                    uint32_t bh0 = bh[q][hsel], bh1 = bh[q][hsel + 1];
                    uint32_t bl0 = bl[q][hsel], bl1 = bl[q][hsel + 1];
                    mma16816(acc[i][jn], ah[i], bh0, bh1);
                    mma16816(acc[i][jn], ah[i], bl0, bl1);
                    mma16816(acc[i][jn], al[i], bh0, bh1);
                }
        }
        __syncthreads();
        if (kc < 2) STAGE1((kc + 2) * 64, bufo);
        CP_COMMIT();
    }
#undef STAGE1

    // epilogue: bias + relu, then bf16 hi/lo split stores
    int r0 = bm + warp_m + (lane >> 2);
    int c0 = bn + warp_n + 2 * (lane & 3);
#pragma unroll
    for (int i = 0; i < 2; i++) {
        int row = r0 + i * 16;
#pragma unroll
        for (int jn = 0; jn < 8; jn++) {
            int col = c0 + jn * 8;
            float bx = b1[col], by = b1[col + 1];
            if (row < NN) {
                float vx = acc[i][jn][0] + bx; vx = vx > 0.f ? vx : 0.f;
                float vy = acc[i][jn][1] + by; vy = vy > 0.f ? vy : 0.f;
                uint32_t hi, lo;
                split2(vx, vy, hi, lo);
                *(uint32_t*)&g_hhi[(size_t)row * 256 + col] = hi;
                *(uint32_t*)&g_hlo[(size_t)row * 256 + col] = lo;
            }
            if (row + 8 < NN) {
                float vx = acc[i][jn][2] + bx; vx = vx > 0.f ? vx : 0.f;
                float vy = acc[i][jn][3] + by; vy = vy > 0.f ? vy : 0.f;
                uint32_t hi, lo;
                split2(vx, vy, hi, lo);
                *(uint32_t*)&g_hhi[(size_t)(row + 8) * 256 + col] = hi;
                *(uint32_t*)&g_hlo[(size_t)(row + 8) * 256 + col] = lo;
            }
        }
    }
}

// ---------------- GEMM2 via mma.sync (cp.async pipe) -------------------------
// Block tile 128x80, 8 warps, warp tile 16x80; K chunks of 64.
#define G2A_H 0
#define G2A_L 16384
#define G2B_H 32768
#define G2B_L 43008
#define BUF2 53248
#define DYN_SMEM2 (2 * BUF2)

__global__ void __launch_bounds__(256, 1) k_gemm2_mma(const float* __restrict__ b2) {
    extern __shared__ char dsm[];
    int tid = threadIdx.x;
    int wid = tid >> 5;
    int lane = tid & 31;
    int bm = blockIdx.x * 128;
    uint32_t dynb = smem_u32(dsm);

    int warp_m = wid * 16;

    uint32_t offA[4], offB[5][4];
    {
        int mat = lane >> 3, rr = lane & 7;
#pragma unroll
        for (int j = 0; j < 4; j++) {
            int row = warp_m + ((mat & 1) << 3) + rr;
            int kb  = j * 16 + ((mat >> 1) << 3);
            offA[j] = SW128(row * 128 + kb * 2);
        }
#pragma unroll
        for (int q = 0; q < 5; q++)
#pragma unroll
            for (int j = 0; j < 4; j++) {
                int n  = q * 16 + ((mat & 2) << 2) + rr;
                int kb = j * 16 + ((mat & 1) << 3);
                offB[q][j] = SW128(n * 128 + kb * 2);
            }
    }

    float acc[10][4];
#pragma unroll
    for (int jn = 0; jn < 10; jn++)
#pragma unroll
        for (int t = 0; t < 4; t++) acc[jn][t] = 0.f;

#define STAGE2(K0, BUFO) do {                                                      \
    _Pragma("unroll")                                                              \
    for (int it = 0; it < 4; it++) {                                               \
        int idx = tid + it * 256;                                                  \
        int row = idx >> 3, seg = idx & 7;                                         \
        int grow = bm + row;                                                       \
        int cl = grow < NN ? grow : (NN - 1);                                      \
        int sz = grow < NN ? 16 : 0;                                               \
        size_t boff = ((size_t)cl * 256 + (K0) + seg * 8) * 2;                     \
        int so = SW128(row * 128 + seg * 16);                                      \
        cp_async16(dynb + (BUFO) + G2A_H + so, (const char*)g_hhi + boff, sz);     \
        cp_async16(dynb + (BUFO) + G2A_L + so, (const char*)g_hlo + boff, sz);     \
    }                                                                              \
    _Pragma("unroll")                                                              \
    for (int it = 0; it < 3; it++) {                                               \
        int idx = tid + it * 256;                                                  \
        if (idx < 640) {                                                           \
            int row = idx >> 3, seg = idx & 7;                                     \
            size_t boff = ((size_t)row * 256 + (K0) + seg * 8) * 2;                \
            int so = SW128(row * 128 + seg * 16);                                  \
            cp_async16(dynb + (BUFO) + G2B_H + so, (const char*)g_w2hi + boff, 16);\
            cp_async16(dynb + (BUFO) + G2B_L + so, (const char*)g_w2lo + boff, 16);\
        }                                                                          \
    }                                                                              \
} while (0)

    STAGE2(0, 0);     CP_COMMIT();
    STAGE2(64, BUF2); CP_COMMIT();

    for (int kc = 0; kc < 4; kc++) {
        uint32_t bufo = (kc & 1) ? BUF2 : 0;
        CP_WAIT1();
        __syncthreads();
#pragma unroll
        for (int j = 0; j < 4; j++) {
            uint32_t ah[4], al[4], bh[5][4], bl[5][4];
            LDSM4(ah, dynb + bufo + G2A_H + offA[j]);
            LDSM4(al, dynb + bufo + G2A_L + offA[j]);
#pragma unroll
            for (int q = 0; q < 5; q++) {
                LDSM4(bh[q], dynb + bufo + G2B_H + offB[q][j]);
                LDSM4(bl[q], dynb + bufo + G2B_L + offB[q][j]);
            }
#pragma unroll
            for (int jn = 0; jn < 10; jn++) {
                int q = jn >> 1, hsel = (jn & 1) * 2;
                uint32_t bh0 = bh[q][hsel], bh1 = bh[q][hsel + 1];
                uint32_t bl0 = bl[q][hsel], bl1 = bl[q][hsel + 1];
                mma16816(acc[jn], ah, bh0, bh1);
                mma16816(acc[jn], ah, bl0, bl1);
                mma16816(acc[jn], al, bh0, bh1);
            }
        }
        __syncthreads();
        if (kc < 2) STAGE2((kc + 2) * 64, bufo);
        CP_COMMIT();
    }
#undef STAGE2

    // epilogue: cols<40 -> p (no bias), cols>=40 -> r (+b2)
    int r0 = bm + warp_m + (lane >> 2);
    int c0 = 2 * (lane & 3);
#pragma unroll
    for (int jn = 0; jn < 10; jn++) {
        int col = c0 + jn * 8;
#pragma unroll
        for (int half = 0; half < 2; half++) {
            int row = r0 + half * 8;
            if (row < NN) {
                float vx = acc[jn][half * 2 + 0];
                float vy = acc[jn][half * 2 + 1];
                if (col < 40) {
                    float2 v = make_float2(vx, vy);
                    *(float2*)&g_p[(size_t)row * 40 + col] = v;
                } else {
                    float2 v = make_float2(vx + b2[col - 40], vy + b2[col - 39]);
                    *(float2*)&g_r[(size_t)row * 40 + (col - 40)] = v;
                }
            }
        }
    }
}

// ---------------- layer-2 aggregation + log_softmax --------------------------
__global__ void k_agg2_lsm(float* __restrict__ out) {
    int warp = (blockIdx.x * blockDim.x + threadIdx.x) >> 5;
    if (warp >= NN) return;
    int lane = threadIdx.x & 31;
    int beg = g_offsets[warp], end = g_offsets[warp + 1];
    bool h1 = lane < 8;
    float a0 = 0.f, a1 = 0.f;
    for (int e = beg; e < end; e++) {
        int s = g_esrc[e];
        const float* ps = g_p + (size_t)s * 40;
        a0 += ps[lane];
        if (h1) a1 += ps[32 + lane];
    }
    float iv = g_invc[warp];
    float v0 = a0 * iv + g_r[(size_t)warp * 40 + lane];
    float v1 = h1 ? (a1 * iv + g_r[(size_t)warp * 40 + 32 + lane]) : -3.0e38f;

    float m = fmaxf(v0, v1);
#pragma unroll
    for (int off = 16; off; off >>= 1)
        m = fmaxf(m, __shfl_xor_sync(0xffffffffu, m, off));
    float ssum = expf(v0 - m) + (h1 ? expf(v1 - m) : 0.f);
#pragma unroll
    for (int off = 16; off; off >>= 1)
        ssum += __shfl_xor_sync(0xffffffffu, ssum, off);
    float lse = m + logf(ssum);

    out[(size_t)warp * 40 + lane] = v0 - lse;
    if (h1) out[(size_t)warp * 40 + 32 + lane] = v1 - lse;
}

// ---------------- launch -----------------------------------------------------
extern "C" void kernel_launch(void* const* d_in, const int* in_sizes, int n_in,
                              void* d_out, int out_size) {
    const float* x   = (const float*)d_in[0];
    const void*  ei  = d_in[1];
    const float* W1l = (const float*)d_in[2];
    const float* W1r = (const float*)d_in[3];
    const float* b1  = (const float*)d_in[4];
    const float* W2l = (const float*)d_in[5];
    const float* W2r = (const float*)d_in[6];
    const float* b2  = (const float*)d_in[7];
    float* out = (float*)d_out;

    cudaFuncSetAttribute(k_gemm1_mma, cudaFuncAttributeMaxDynamicSharedMemorySize,
                         DYN_SMEM1);
    cudaFuncSetAttribute(k_gemm2_mma, cudaFuncAttributeMaxDynamicSharedMemorySize,
                         DYN_SMEM2);

    k_detect<<<1, 1024>>>((const int*)ei);
    k_zero_counts<<<(NN + 255) / 256, 256>>>();
    k_count<<<(NE + 255) / 256, 256>>>(ei);
    k_scanA<<<NB, 256>>>();
    k_scanB<<<1, 256>>>();
    k_scanC<<<NB, 256>>>();
    k_scatter<<<(NE + 255) / 256, 256>>>(ei);
    k_prep<<<336 + (NN * 32 + 255) / 256, 256>>>(W1l, W1r, W2l, W2r, x);
    k_agg1<<<(NN + 7) / 8, 256>>>(x);
    dim3 g1((NN + 127) / 128, 2);
    k_gemm1_mma<<<g1, 256, DYN_SMEM1>>>(b1);
    k_gemm2_mma<<<(NN + 127) / 128, 256, DYN_SMEM2>>>(b2);
    k_agg2_lsm<<<(NN + 7) / 8, 256>>>(out);
}

// round 8
// speedup vs baseline: 2.4522x; 1.0260x over previous
#include <cuda_runtime.h>
#include <cuda_bf16.h>
#include <math.h>
#include <cstdint>

#define NN   50000
#define NE   800000
#define IND  128
#define HID  256
#define OUTD 40
#define NB   ((NN + 255) / 256)   // 196 scan blocks

// ---------------- scratch ----------------------------------------------------
__device__ int   g_is64;
__device__ int   g_counts[NN];
__device__ int   g_offsets[NN + 1];
__device__ int   g_cursor[NN];
__device__ int   g_esrc[NE];
__device__ float g_invc[NN];
__device__ int   g_bsum[NB];
__device__ int   g_done1 = 0;
__device__ int   g_done2 = 0;
__device__ __align__(16) __nv_bfloat16 g_a_hi[(size_t)NN * HID];  // [agg|x] hi
__device__ __align__(16) __nv_bfloat16 g_a_lo[(size_t)NN * HID];  // [agg|x] lo
__device__ __align__(16) __nv_bfloat16 g_w1hi[(size_t)HID * HID]; // W1^T hi [n][k]
__device__ __align__(16) __nv_bfloat16 g_w1lo[(size_t)HID * HID]; // W1^T lo [n][k]
__device__ __align__(16) __nv_bfloat16 g_hhi[(size_t)NN * HID];   // h hi [NN][256]
__device__ __align__(16) __nv_bfloat16 g_hlo[(size_t)NN * HID];   // h lo
__device__ __align__(16) __nv_bfloat16 g_w2hi[(size_t)80 * HID];  // W2^T hi [80][256]
__device__ __align__(16) __nv_bfloat16 g_w2lo[(size_t)80 * HID];  // W2^T lo
__device__ __align__(16) float g_p[(size_t)NN * OUTD];
__device__ __align__(16) float g_r[(size_t)NN * OUTD];

// ---------------- helpers ----------------------------------------------------
__device__ __forceinline__ uint32_t smem_u32(const void* p) {
    uint32_t a;
    asm("{ .reg .u64 t; cvta.to.shared.u64 t, %1; cvt.u32.u64 %0, t; }"
        : "=r"(a) : "l"(p));
    return a;
}

#define SW128(o) ((o) ^ (((o) >> 3) & 0x70))

#define LDSM4(R, ADDR)                                                           \
    asm volatile("ldmatrix.sync.aligned.m8n8.x4.shared.b16 {%0,%1,%2,%3}, [%4];" \
        : "=r"((R)[0]), "=r"((R)[1]), "=r"((R)[2]), "=r"((R)[3]) : "r"(ADDR))

__device__ __forceinline__ void mma16816(float* c, const uint32_t* a,
                                         uint32_t b0, uint32_t b1) {
    asm volatile(
        "mma.sync.aligned.m16n8k16.row.col.f32.bf16.bf16.f32 "
        "{%0,%1,%2,%3}, {%4,%5,%6,%7}, {%8,%9}, {%0,%1,%2,%3};"
        : "+f"(c[0]), "+f"(c[1]), "+f"(c[2]), "+f"(c[3])
        : "r"(a[0]), "r"(a[1]), "r"(a[2]), "r"(a[3]), "r"(b0), "r"(b1));
}

__device__ __forceinline__ void cp_async16(uint32_t dst, const void* src, int srcsz) {
    asm volatile("cp.async.cg.shared.global [%0], [%1], 16, %2;"
                 :: "r"(dst), "l"(src), "r"(srcsz) : "memory");
}
#define CP_COMMIT() asm volatile("cp.async.commit_group;" ::: "memory")
#define CP_WAIT1()  asm volatile("cp.async.wait_group 1;" ::: "memory")

__device__ __forceinline__ int edge_at(const void* ei, int idx) {
    if (g_is64) return (int)((const long long*)ei)[idx];
    return ((const int*)ei)[idx];
}

// ---------------- bf16 split helpers -----------------------------------------
__device__ __forceinline__ void split4(float4 v, uint2& hi, uint2& lo) {
    __nv_bfloat16 h0 = __float2bfloat16(v.x);
    __nv_bfloat16 h1 = __float2bfloat16(v.y);
    __nv_bfloat16 h2 = __float2bfloat16(v.z);
    __nv_bfloat16 h3 = __float2bfloat16(v.w);
    __nv_bfloat16 l0 = __float2bfloat16(v.x - __bfloat162float(h0));
    __nv_bfloat16 l1 = __float2bfloat16(v.y - __bfloat162float(h1));
    __nv_bfloat16 l2 = __float2bfloat16(v.z - __bfloat162float(h2));
    __nv_bfloat16 l3 = __float2bfloat16(v.w - __bfloat162float(h3));
    hi.x = (uint32_t)__bfloat16_as_ushort(h0) | ((uint32_t)__bfloat16_as_ushort(h1) << 16);
    hi.y = (uint32_t)__bfloat16_as_ushort(h2) | ((uint32_t)__bfloat16_as_ushort(h3) << 16);
    lo.x = (uint32_t)__bfloat16_as_ushort(l0) | ((uint32_t)__bfloat16_as_ushort(l1) << 16);
    lo.y = (uint32_t)__bfloat16_as_ushort(l2) | ((uint32_t)__bfloat16_as_ushort(l3) << 16);
}

__device__ __forceinline__ void split2(float x, float y, uint32_t& hi, uint32_t& lo) {
    __nv_bfloat16 hx = __float2bfloat16(x), hy = __float2bfloat16(y);
    __nv_bfloat16 lx = __float2bfloat16(x - __bfloat162float(hx));
    __nv_bfloat16 ly = __float2bfloat16(y - __bfloat162float(hy));
    hi = (uint32_t)__bfloat16_as_ushort(hx) | ((uint32_t)__bfloat16_as_ushort(hy) << 16);
    lo = (uint32_t)__bfloat16_as_ushort(lx) | ((uint32_t)__bfloat16_as_ushort(ly) << 16);
}

// ---------------- k_init: detect (block 0) + zero counts (blocks 1..196) -----
__global__ void k_init(const int* __restrict__ ei32) {
    int b = blockIdx.x;
    int tid = threadIdx.x;
    if (b == 0) {
        __shared__ int bad;
        if (tid == 0) bad = 0;
        __syncthreads();
        if (ei32[2 * tid + 1] != 0) atomicOr(&bad, 1);
        __syncthreads();
        if (tid == 0) g_is64 = bad ? 0 : 1;
    } else {
        int i = (b - 1) * 256 + tid;
        if (i < NN) g_counts[i] = 0;
    }
}

// ---------------- k_count_prep: edge count ∥ W1/W2/x bf16-split --------------
// blocks [0,3125): count; [3125,3381): W1; [3381,3461): W2; [3461,9711): x
#define CPB_COUNT 3125
#define CPB_W1    (CPB_COUNT + 256)
#define CPB_W2    (CPB_W1 + 80)
#define CPB_X     (CPB_W2 + 6250)

__global__ void k_count_prep(const void* __restrict__ ei,
                             const float* __restrict__ W1l, const float* __restrict__ W1r,
                             const float* __restrict__ W2l, const float* __restrict__ W2r,
                             const float* __restrict__ x) {
    int b = blockIdx.x;
    int tid = threadIdx.x;
    if (b < CPB_COUNT) {
        int e = b * 256 + tid;
        if (e < NE) atomicAdd(&g_counts[edge_at(ei, NE + e)], 1);
    } else if (b < CPB_W1) {
        int idx = (b - CPB_COUNT) * 256 + tid;
        int n = idx >> 8, k = idx & 255;
        float w = (k < 128) ? W1l[(size_t)k * 256 + n]
                            : W1r[(size_t)(k - 128) * 256 + n];
        __nv_bfloat16 h = __float2bfloat16(w);
        __nv_bfloat16 l = __float2bfloat16(w - __bfloat162float(h));
        g_w1hi[(size_t)n * 256 + k] = h;
        g_w1lo[(size_t)n * 256 + k] = l;
    } else if (b < CPB_W2) {
        int idx = (b - CPB_W1) * 256 + tid;
        int n = idx >> 8, k = idx & 255;
        float w = (n < 40) ? W2l[(size_t)k * 40 + n]
                           : W2r[(size_t)k * 40 + (n - 40)];
        __nv_bfloat16 h = __float2bfloat16(w);
        __nv_bfloat16 l = __float2bfloat16(w - __bfloat162float(h));
        g_w2hi[(size_t)n * 256 + k] = h;
        g_w2lo[(size_t)n * 256 + k] = l;
    } else {
        int idx = (b - CPB_W2) * 256 + tid;
        if (idx >= NN * 32) return;
        int row = idx >> 5, c4 = idx & 31;
        float4 v = ((const float4*)x)[(size_t)row * 32 + c4];
        uint2 hi, lo;
        split4(v, hi, lo);
        *(uint2*)&g_a_hi[(size_t)row * 256 + 128 + c4 * 4] = hi;
        *(uint2*)&g_a_lo[(size_t)row * 256 + 128 + c4 * 4] = lo;
    }
}

// ---------------- k_scan: fused A+B+C (publish, spin, per-block prefix) ------
// returns exclusive prefix within block; helper also leaves total via tid 255
__device__ __forceinline__ int block_excl_scan(int c, int t) {
    int lane = t & 31, w = t >> 5;
    int v = c;
#pragma unroll
    for (int off = 1; off < 32; off <<= 1) {
        int n = __shfl_up_sync(0xffffffffu, v, off);
        if (lane >= off) v += n;
    }
    __shared__ int ws[8];
    if (lane == 31) ws[w] = v;
    __syncthreads();
    if (w == 0 && lane < 8) {
        int s = ws[lane];
#pragma unroll
        for (int off = 1; off < 8; off <<= 1) {
            int n = __shfl_up_sync(0x000000ffu, s, off);
            if (lane >= off) s += n;
        }
        ws[lane] = s;
    }
    __syncthreads();
    return v - c + (w > 0 ? ws[w - 1] : 0);
}

__global__ void k_scan() {
    int b = blockIdx.x, tid = threadIdx.x;
    int i = b * 256 + tid;
    int c = (i < NN) ? g_counts[i] : 0;
    int e = block_excl_scan(c, tid);

    // publish block total, count arrivals
    if (tid == 255) {
        g_bsum[b] = e + c;
        __threadfence();
        atomicAdd(&g_done1, 1);
    }
    // spin until all totals visible
    if (tid == 0) {
        while (*(volatile int*)&g_done1 < NB) {}
    }
    __syncthreads();
    __threadfence();

    // prefix over previous blocks (b <= 195 < 256)
    int v = (tid < b) ? g_bsum[tid] : 0;
    int lane = tid & 31, w = tid >> 5;
#pragma unroll
    for (int off = 16; off; off >>= 1) v += __shfl_xor_sync(0xffffffffu, v, off);
    __shared__ int rs[8];
    if (lane == 0) rs[w] = v;
    __syncthreads();
    __shared__ int pre;
    if (tid == 0) {
        int s = 0;
#pragma unroll
        for (int k = 0; k < 8; k++) s += rs[k];
        pre = s;
    }
    __syncthreads();

    if (i < NN) {
        int off = pre + e;
        g_offsets[i] = off;
        g_cursor[i]  = off;
        g_invc[i]    = 1.0f / (float)(c > 1 ? c : 1);
    }
    if (b == NB - 1 && tid == 255) g_offsets[NN] = NE;

    // deterministic reset for graph replay
    if (tid == 0) {
        int t2 = atomicAdd(&g_done2, 1);
        if (t2 == NB - 1) { g_done1 = 0; g_done2 = 0; }
    }
}

__global__ void k_scatter(const void* __restrict__ ei) {
    int e = blockIdx.x * blockDim.x + threadIdx.x;
    if (e < NE) {
        int s = edge_at(ei, e);
        int d = edge_at(ei, NE + e);
        g_esrc[atomicAdd(&g_cursor[d], 1)] = s;
    }
}

// ---------------- layer-1 aggregation (bf16 hi/lo cols 0..127) ---------------
__global__ void k_agg1(const float* __restrict__ x) {
    int warp = (blockIdx.x * blockDim.x + threadIdx.x) >> 5;
    if (warp >= NN) return;
    int lane = threadIdx.x & 31;
    int beg = g_offsets[warp], end = g_offsets[warp + 1];
    const float4* __restrict__ x4 = (const float4*)x;
    float4 acc = make_float4(0.f, 0.f, 0.f, 0.f);
    int e = beg;
    for (; e + 1 < end; e += 2) {
        int s0 = g_esrc[e];
        int s1 = g_esrc[e + 1];
        float4 v0 = x4[(size_t)s0 * 32 + lane];
        float4 v1 = x4[(size_t)s1 * 32 + lane];
        acc.x += v0.x + v1.x; acc.y += v0.y + v1.y;
        acc.z += v0.z + v1.z; acc.w += v0.w + v1.w;
    }
    if (e < end) {
        int s0 = g_esrc[e];
        float4 v0 = x4[(size_t)s0 * 32 + lane];
        acc.x += v0.x; acc.y += v0.y; acc.z += v0.z; acc.w += v0.w;
    }
    float iv = g_invc[warp];
    float4 o = make_float4(acc.x * iv, acc.y * iv, acc.z * iv, acc.w * iv);
    uint2 hi, lo;
    split4(o, hi, lo);
    *(uint2*)&g_a_hi[(size_t)warp * 256 + lane * 4] = hi;
    *(uint2*)&g_a_lo[(size_t)warp * 256 + lane * 4] = lo;
}

// ---------------- GEMM1 via mma.sync (bf16 3-pass split, cp.async pipe) ------
#define GA_H 0
#define GA_L 16384
#define GB_H 32768
#define GB_L 49152
#define BUF1 65536
#define DYN_SMEM1 (2 * BUF1)

__global__ void __launch_bounds__(256, 1) k_gemm1_mma(const float* __restrict__ b1) {
    extern __shared__ char dsm[];
    int tid = threadIdx.x;
    int wid = tid >> 5;
    int lane = tid & 31;
    int bm = blockIdx.x * 128;
    int bn = blockIdx.y * 128;
    uint32_t dynb = smem_u32(dsm);

    int warp_m = (wid & 3) * 32;
    int warp_n = (wid >> 2) * 64;

    uint32_t offA[2][4], offB[4][4];
    {
        int mat = lane >> 3, rr = lane & 7;
#pragma unroll
        for (int i = 0; i < 2; i++)
#pragma unroll
            for (int j = 0; j < 4; j++) {
                int row = warp_m + i * 16 + ((mat & 1) << 3) + rr;
                int kb  = j * 16 + ((mat >> 1) << 3);
                offA[i][j] = SW128(row * 128 + kb * 2);
            }
#pragma unroll
        for (int q = 0; q < 4; q++)
#pragma unroll
            for (int j = 0; j < 4; j++) {
                int n  = warp_n + q * 16 + ((mat & 2) << 2) + rr;
                int kb = j * 16 + ((mat & 1) << 3);
                offB[q][j] = SW128(n * 128 + kb * 2);
            }
    }

    float acc[2][8][4];
#pragma unroll
    for (int i = 0; i < 2; i++)
#pragma unroll
        for (int jn = 0; jn < 8; jn++)
#pragma unroll
            for (int t = 0; t < 4; t++) acc[i][jn][t] = 0.f;

#define STAGE1(K0, BUFO) do {                                                      \
    _Pragma("unroll")                                                              \
    for (int it = 0; it < 4; it++) {                                               \
        int idx = tid + it * 256;                                                  \
        int row = idx >> 3, seg = idx & 7;                                         \
        int grow = bm + row;                                                       \
        int cl = grow < NN ? grow : (NN - 1);                                      \
        int sz = grow < NN ? 16 : 0;                                               \
        size_t boff = ((size_t)cl * 256 + (K0) + seg * 8) * 2;                     \
        int so = SW128(row * 128 + seg * 16);                                      \
        cp_async16(dynb + (BUFO) + GA_H + so, (const char*)g_a_hi + boff, sz);     \
        cp_async16(dynb + (BUFO) + GA_L + so, (const char*)g_a_lo + boff, sz);     \
    }                                                                              \
    _Pragma("unroll")                                                              \
    for (int it = 0; it < 4; it++) {                                               \
        int idx = tid + it * 256;                                                  \
        int row = idx >> 3, seg = idx & 7;                                         \
        size_t boff = ((size_t)(bn + row) * 256 + (K0) + seg * 8) * 2;             \
        int so = SW128(row * 128 + seg * 16);                                      \
        cp_async16(dynb + (BUFO) + GB_H + so, (const char*)g_w1hi + boff, 16);     \
        cp_async16(dynb + (BUFO) + GB_L + so, (const char*)g_w1lo + boff, 16);     \
    }                                                                              \
} while (0)

    STAGE1(0, 0);     CP_COMMIT();
    STAGE1(64, BUF1); CP_COMMIT();

    for (int kc = 0; kc < 4; kc++) {
        uint32_t bufo = (kc & 1) ? BUF1 : 0;
        CP_WAIT1();
        __syncthreads();
#pragma unroll
        for (int j = 0; j < 4; j++) {
            uint32_t ah[2][4], al[2][4], bh[4][4], bl[4][4];
#pragma unroll
            for (int i = 0; i < 2; i++) {
                LDSM4(ah[i], dynb + bufo + GA_H + offA[i][j]);
                LDSM4(al[i], dynb + bufo + GA_L + offA[i][j]);
            }
#pragma unroll
            for (int q = 0; q < 4; q++) {
                LDSM4(bh[q], dynb + bufo + GB_H + offB[q][j]);
                LDSM4(bl[q], dynb + bufo + GB_L + offB[q][j]);
            }
#pragma unroll
            for (int i = 0; i < 2; i++)
#pragma unroll
                for (int jn = 0; jn < 8; jn++) {
                    int q = jn >> 1, hsel = (jn & 1) * 2;
                    uint32_t bh0 = bh[q][hsel], bh1 = bh[q][hsel + 1];
                    uint32_t bl0 = bl[q][hsel], bl1 = bl[q][hsel + 1];
                    mma16816(acc[i][jn], ah[i], bh0, bh1);
                    mma16816(acc[i][jn], ah[i], bl0, bl1);
                    mma16816(acc[i][jn], al[i], bh0, bh1);
                }
        }
        __syncthreads();
        if (kc < 2) STAGE1((kc + 2) * 64, bufo);
        CP_COMMIT();
    }
#undef STAGE1

    int r0 = bm + warp_m + (lane >> 2);
    int c0 = bn + warp_n + 2 * (lane & 3);
#pragma unroll
    for (int i = 0; i < 2; i++) {
        int row = r0 + i * 16;
#pragma unroll
        for (int jn = 0; jn < 8; jn++) {
            int col = c0 + jn * 8;
            float bx = b1[col], by = b1[col + 1];
            if (row < NN) {
                float vx = acc[i][jn][0] + bx; vx = vx > 0.f ? vx : 0.f;
                float vy = acc[i][jn][1] + by; vy = vy > 0.f ? vy : 0.f;
                uint32_t hi, lo;
                split2(vx, vy, hi, lo);
                *(uint32_t*)&g_hhi[(size_t)row * 256 + col] = hi;
                *(uint32_t*)&g_hlo[(size_t)row * 256 + col] = lo;
            }
            if (row + 8 < NN) {
                float vx = acc[i][jn][2] + bx; vx = vx > 0.f ? vx : 0.f;
                float vy = acc[i][jn][3] + by; vy = vy > 0.f ? vy : 0.f;
                uint32_t hi, lo;
                split2(vx, vy, hi, lo);
                *(uint32_t*)&g_hhi[(size_t)(row + 8) * 256 + col] = hi;
                *(uint32_t*)&g_hlo[(size_t)(row + 8) * 256 + col] = lo;
            }
        }
    }
}

// ---------------- GEMM2 via mma.sync (cp.async pipe) -------------------------
#define G2A_H 0
#define G2A_L 16384
#define G2B_H 32768
#define G2B_L 43008
#define BUF2 53248
#define DYN_SMEM2 (2 * BUF2)

__global__ void __launch_bounds__(256, 1) k_gemm2_mma(const float* __restrict__ b2) {
    extern __shared__ char dsm[];
    int tid = threadIdx.x;
    int wid = tid >> 5;
    int lane = tid & 31;
    int bm = blockIdx.x * 128;
    uint32_t dynb = smem_u32(dsm);

    int warp_m = wid * 16;

    uint32_t offA[4], offB[5][4];
    {
        int mat = lane >> 3, rr = lane & 7;
#pragma unroll
        for (int j = 0; j < 4; j++) {
            int row = warp_m + ((mat & 1) << 3) + rr;
            int kb  = j * 16 + ((mat >> 1) << 3);
            offA[j] = SW128(row * 128 + kb * 2);
        }
#pragma unroll
        for (int q = 0; q < 5; q++)
#pragma unroll
            for (int j = 0; j < 4; j++) {
                int n  = q * 16 + ((mat & 2) << 2) + rr;
                int kb = j * 16 + ((mat & 1) << 3);
                offB[q][j] = SW128(n * 128 + kb * 2);
            }
    }

    float acc[10][4];
#pragma unroll
    for (int jn = 0; jn < 10; jn++)
#pragma unroll
        for (int t = 0; t < 4; t++) acc[jn][t] = 0.f;

#define STAGE2(K0, BUFO) do {                                                      \
    _Pragma("unroll")                                                              \
    for (int it = 0; it < 4; it++) {                                               \
        int idx = tid + it * 256;                                                  \
        int row = idx >> 3, seg = idx & 7;                                         \
        int grow = bm + row;                                                       \
        int cl = grow < NN ? grow : (NN - 1);                                      \
        int sz = grow < NN ? 16 : 0;                                               \
        size_t boff = ((size_t)cl * 256 + (K0) + seg * 8) * 2;                     \
        int so = SW128(row * 128 + seg * 16);                                      \
        cp_async16(dynb + (BUFO) + G2A_H + so, (const char*)g_hhi + boff, sz);     \
        cp_async16(dynb + (BUFO) + G2A_L + so, (const char*)g_hlo + boff, sz);     \
    }                                                                              \
    _Pragma("unroll")                                                              \
    for (int it = 0; it < 3; it++) {                                               \
        int idx = tid + it * 256;                                                  \
        if (idx < 640) {                                                           \
            int row = idx >> 3, seg = idx & 7;                                     \
            size_t boff = ((size_t)row * 256 + (K0) + seg * 8) * 2;                \
            int so = SW128(row * 128 + seg * 16);                                  \
            cp_async16(dynb + (BUFO) + G2B_H + so, (const char*)g_w2hi + boff, 16);\
            cp_async16(dynb + (BUFO) + G2B_L + so, (const char*)g_w2lo + boff, 16);\
        }                                                                          \
    }                                                                              \
} while (0)

    STAGE2(0, 0);     CP_COMMIT();
    STAGE2(64, BUF2); CP_COMMIT();

    for (int kc = 0; kc < 4; kc++) {
        uint32_t bufo = (kc & 1) ? BUF2 : 0;
        CP_WAIT1();
        __syncthreads();
#pragma unroll
        for (int j = 0; j < 4; j++) {
            uint32_t ah[4], al[4], bh[5][4], bl[5][4];
            LDSM4(ah, dynb + bufo + G2A_H + offA[j]);
            LDSM4(al, dynb + bufo + G2A_L + offA[j]);
#pragma unroll
            for (int q = 0; q < 5; q++) {
                LDSM4(bh[q], dynb + bufo + G2B_H + offB[q][j]);
                LDSM4(bl[q], dynb + bufo + G2B_L + offB[q][j]);
            }
#pragma unroll
            for (int jn = 0; jn < 10; jn++) {
                int q = jn >> 1, hsel = (jn & 1) * 2;
                uint32_t bh0 = bh[q][hsel], bh1 = bh[q][hsel + 1];
                uint32_t bl0 = bl[q][hsel], bl1 = bl[q][hsel + 1];
                mma16816(acc[jn], ah, bh0, bh1);
                mma16816(acc[jn], ah, bl0, bl1);
                mma16816(acc[jn], al, bh0, bh1);
            }
        }
        __syncthreads();
        if (kc < 2) STAGE2((kc + 2) * 64, bufo);
        CP_COMMIT();
    }
#undef STAGE2

    int r0 = bm + warp_m + (lane >> 2);
    int c0 = 2 * (lane & 3);
#pragma unroll
    for (int jn = 0; jn < 10; jn++) {
        int col = c0 + jn * 8;
#pragma unroll
        for (int half = 0; half < 2; half++) {
            int row = r0 + half * 8;
            if (row < NN) {
                float vx = acc[jn][half * 2 + 0];
                float vy = acc[jn][half * 2 + 1];
                if (col < 40) {
                    float2 v = make_float2(vx, vy);
                    *(float2*)&g_p[(size_t)row * 40 + col] = v;
                } else {
                    float2 v = make_float2(vx + b2[col - 40], vy + b2[col - 39]);
                    *(float2*)&g_r[(size_t)row * 40 + (col - 40)] = v;
                }
            }
        }
    }
}

// ---------------- layer-2 aggregation + log_softmax --------------------------
__global__ void k_agg2_lsm(float* __restrict__ out) {
    int warp = (blockIdx.x * blockDim.x + threadIdx.x) >> 5;
    if (warp >= NN) return;
    int lane = threadIdx.x & 31;
    int beg = g_offsets[warp], end = g_offsets[warp + 1];
    bool h1 = lane < 8;
    float a0 = 0.f, a1 = 0.f;
    for (int e = beg; e < end; e++) {
        int s = g_esrc[e];
        const float* ps = g_p + (size_t)s * 40;
        a0 += ps[lane];
        if (h1) a1 += ps[32 + lane];
    }
    float iv = g_invc[warp];
    float v0 = a0 * iv + g_r[(size_t)warp * 40 + lane];
    float v1 = h1 ? (a1 * iv + g_r[(size_t)warp * 40 + 32 + lane]) : -3.0e38f;

    float m = fmaxf(v0, v1);
#pragma unroll
    for (int off = 16; off; off >>= 1)
        m = fmaxf(m, __shfl_xor_sync(0xffffffffu, m, off));
    float ssum = expf(v0 - m) + (h1 ? expf(v1 - m) : 0.f);
#pragma unroll
    for (int off = 16; off; off >>= 1)
        ssum += __shfl_xor_sync(0xffffffffu, ssum, off);
    float lse = m + logf(ssum);

    out[(size_t)warp * 40 + lane] = v0 - lse;
    if (h1) out[(size_t)warp * 40 + 32 + lane] = v1 - lse;
}

// ---------------- launch -----------------------------------------------------
extern "C" void kernel_launch(void* const* d_in, const int* in_sizes, int n_in,
                              void* d_out, int out_size) {
    const float* x   = (const float*)d_in[0];
    const void*  ei  = d_in[1];
    const float* W1l = (const float*)d_in[2];
    const float* W1r = (const float*)d_in[3];
    const float* b1  = (const float*)d_in[4];
    const float* W2l = (const float*)d_in[5];
    const float* W2r = (const float*)d_in[6];
    const float* b2  = (const float*)d_in[7];
    float* out = (float*)d_out;

    cudaFuncSetAttribute(k_gemm1_mma, cudaFuncAttributeMaxDynamicSharedMemorySize,
                         DYN_SMEM1);
    cudaFuncSetAttribute(k_gemm2_mma, cudaFuncAttributeMaxDynamicSharedMemorySize,
                         DYN_SMEM2);

    k_init<<<1 + NB, 256>>>((const int*)ei);
    k_count_prep<<<CPB_X, 256>>>(ei, W1l, W1r, W2l, W2r, x);
    k_scan<<<NB, 256>>>();
    k_scatter<<<(NE + 255) / 256, 256>>>(ei);
    k_agg1<<<(NN + 7) / 8, 256>>>(x);
    dim3 g1((NN + 127) / 128, 2);
    k_gemm1_mma<<<g1, 256, DYN_SMEM1>>>(b1);
    k_gemm2_mma<<<(NN + 127) / 128, 256, DYN_SMEM2>>>(b2);
    k_agg2_lsm<<<(NN + 7) / 8, 256>>>(out);
}